// round 5
// baseline (speedup 1.0000x reference)
#include <cuda_runtime.h>
#include <cuda_bf16.h>
#include <cstdint>

// Problem: B=8, C=16, H=W=64, O=32, K=3, S=1, P=1, G=8, D=144, Kdim=1152
// basis(v,g) = exp(-((v-grid_g)/h)^2) = ex2(-u^2), u = v*C1 + C2[g]
#define C1F 2.1019642153762872f

__device__ __constant__ float C2F[8] = {
     4.2039284307525744f,  3.0028060219661250f,  1.8016836131796750f,  0.6005612043932250f,
    -0.6005612043932250f, -1.8016836131796750f, -3.0028060219661250f, -4.2039284307525744f
};

// Device scratch (no allocation allowed)
__device__ __align__(16) unsigned char g_Wfrag[147456];   // bf16 hi/lo B fragments
__device__ __align__(16) float2 g_part[32 * 128];         // per-(o, cta) sum/sumsq
__device__ unsigned g_bar0 = 0, g_bar1 = 0;               // monotone barrier counters

// ---------------------------------------------------------------------------
// helpers
// ---------------------------------------------------------------------------
__device__ __forceinline__ float ex2f(float m) {
    float r; asm("ex2.approx.f32 %0, %1;" : "=f"(r) : "f"(m)); return r;
}
__device__ __forceinline__ uint32_t pack_hi(float b0, float b1) {
    uint32_t r, u0 = __float_as_uint(b0), u1 = __float_as_uint(b1);
    asm("prmt.b32 %0, %1, %2, 0x7632;" : "=r"(r) : "r"(u0), "r"(u1));
    return r;
}
__device__ __forceinline__ uint32_t pack_lo(float b0, float b1) {
    float l0 = b0 - __uint_as_float(__float_as_uint(b0) & 0xFFFF0000u);
    float l1 = b1 - __uint_as_float(__float_as_uint(b1) & 0xFFFF0000u);
    uint32_t r;
    asm("cvt.rn.bf16x2.f32 %0, %1, %2;" : "=r"(r) : "f"(l1), "f"(l0));
    return r;
}
__device__ __forceinline__ void mma16816(float* c, const uint32_t* a, uint32_t b0, uint32_t b1) {
    asm volatile(
        "mma.sync.aligned.m16n8k16.row.col.f32.bf16.bf16.f32 "
        "{%0,%1,%2,%3}, {%4,%5,%6,%7}, {%8,%9}, {%0,%1,%2,%3};"
        : "+f"(c[0]), "+f"(c[1]), "+f"(c[2]), "+f"(c[3])
        : "r"(a[0]), "r"(a[1]), "r"(a[2]), "r"(a[3]), "r"(b0), "r"(b1));
}
__device__ __forceinline__ uint32_t smem_u32(const void* p) {
    uint32_t a;
    asm("{ .reg .u64 t; cvta.to.shared.u64 t, %1; cvt.u32.u64 %0, t; }" : "=r"(a) : "l"(p));
    return a;
}

// Grid barrier over exactly 128 co-resident CTAs. Monotone counter: never
// reset, so it is replay-safe under CUDA graphs (2^32 % 128 == 0).
__device__ __forceinline__ void grid_barrier(unsigned* ctr) {
    __threadfence();            // make this CTA's prior writes GPU-visible
    __syncthreads();
    if (threadIdx.x == 0) {
        unsigned prev = atomicAdd(ctr, 1u);
        unsigned target = ((prev >> 7) + 1u) << 7;   // next multiple of 128
        unsigned v;
        do {
            asm volatile("ld.acquire.gpu.global.u32 %0, [%1];" : "=r"(v) : "l"(ctr));
        } while ((int)(v - target) < 0);
    }
    __syncthreads();
}

// ---------------------------------------------------------------------------
// Single fused kernel. grid = 128 CTAs x 256 threads, 1 CTA/SM (co-resident).
// CTA = image b (blockIdx>>4), 4 output rows (blockIdx&15)*4.
// Stage 1: 1/128 slice of Wsum reduce + bf16 hi/lo split + fragment pack.
// Stage 2: Phi tile (basis hi/lo, computed once per x element).
//   [grid barrier 0]
// Stage 3: 72 k-chunks x 24 mma.sync (pass-major for RAW distance 8).
// Stage 4: per-o partial stats from registers -> g_part.
//   [grid barrier 1]
// Stage 5: BN params (identical deterministic reduce in every CTA), apply
//          in registers, store straight to d_out.
// ---------------------------------------------------------------------------
#define PHI_R 2112                      // 66 * 32 bytes
#define PHI_C 12672                     // 6 * PHI_R
#define SMEM_PHI 202752                 // 16 * PHI_C

__global__ void __launch_bounds__(256, 1) kan_fused(
    const float* __restrict__ x, const float* __restrict__ W,
    const float* __restrict__ gamma, const float* __restrict__ beta,
    float* __restrict__ out)
{
    extern __shared__ char smem[];
    __shared__ float sred[8][4][2][2][4];   // [warp][nt][h][S/Q][gp]
    __shared__ float2 bnp[32];

    const uint32_t sb = smem_u32(smem);
    const int tid = threadIdx.x;
    const int cta = blockIdx.x;
    const int b   = cta >> 4;
    const int r0  = (cta & 15) << 2;

    // ---------------- Stage 1: Wsum slice (o fixed, 288 k-values) ----------
    {
        const int o  = cta >> 2;
        const int k0 = (cta & 3) * 288;
#pragma unroll 1
        for (int i = tid; i < 288; i += 256) {
            const int k = k0 + i;
            const float* p = W + (size_t)o * 165888 + k;
            float a0 = 0.f, a1 = 0.f, a2 = 0.f, a3 = 0.f;
#pragma unroll
            for (int d = 0; d < 144; d += 4) {
                a0 += p[(d + 0) * 1152];
                a1 += p[(d + 1) * 1152];
                a2 += p[(d + 2) * 1152];
                a3 += p[(d + 3) * 1152];
            }
            float s = (a0 + a1) + (a2 + a3);

            uint32_t sbits = __float_as_uint(s);
            unsigned short hib = (unsigned short)(sbits >> 16);
            float hif = __uint_as_float(sbits & 0xFFFF0000u);
            __nv_bfloat16 lo = __float2bfloat16(s - hif);

            int kc   = k >> 4;
            int kl   = k & 15;
            int slot = kl >> 1;
            int hi4  = slot >> 2;
            int s2   = slot & 3;
            int half = kl & 1;
            int base = kc * 2048 + o * 64 + s2 * 16;
            *(unsigned short*)(g_Wfrag + base + hi4 * 4 + half * 2)     = hib;
            *(unsigned short*)(g_Wfrag + base + 8 + hi4 * 4 + half * 2) = *(unsigned short*)&lo;
        }
    }

    // ---------------- Stage 2: Phi tile (rows r0-1..r0+4, cols -1..64) -----
#pragma unroll 1
    for (int idx = tid; idx < 6336; idx += 256) {
        int c   = idx / 396;
        int rem = idx - c * 396;
        int r   = rem / 66;
        int col = rem - r * 66;
        int y  = r0 - 1 + r;
        int xx = col - 1;
        float v = 0.f;
        if ((unsigned)y < 64u && (unsigned)xx < 64u)
            v = x[(((b * 16 + c) << 6) + y) * 64 + xx];
        float bb[8];
#pragma unroll
        for (int g = 0; g < 8; ++g) {
            float u = fmaf(v, C1F, C2F[g]);
            bb[g] = ex2f(__fmul_rn(u, -u));
        }
        uint32_t hw[4], lw[4];
#pragma unroll
        for (int i = 0; i < 4; ++i) {
            hw[i] = pack_hi(bb[2 * i], bb[2 * i + 1]);
            lw[i] = pack_lo(bb[2 * i], bb[2 * i + 1]);
        }
        uint32_t a = sb + c * PHI_C + r * PHI_R + col * 32;
        asm volatile("st.shared.v4.b32 [%0], {%1,%2,%3,%4};"
                     :: "r"(a), "r"(hw[0]), "r"(lw[0]), "r"(hw[1]), "r"(lw[1]) : "memory");
        asm volatile("st.shared.v4.b32 [%0+16], {%1,%2,%3,%4};"
                     :: "r"(a), "r"(hw[2]), "r"(lw[2]), "r"(hw[3]), "r"(lw[3]) : "memory");
    }

    grid_barrier(&g_bar0);    // Wfrag globally ready; Phi smem ready (syncthreads)

    // ---------------- Stage 3: mma mainloop --------------------------------
    const int lane = tid & 31;
    const int w    = tid >> 5;
    const int prow = w >> 1;
    const int pc   = (w & 1) << 5;
    const int qr   = lane >> 2;
    const int gp   = lane & 3;

    const uint32_t abase = sb + (uint32_t)prow * PHI_R + (uint32_t)(pc + qr) * 32 + (uint32_t)gp * 8;
    const uint4* wq = ((const uint4*)g_Wfrag) + lane;   // plain loads (written this kernel)

    float acc[2][4][4];
#pragma unroll
    for (int t = 0; t < 2; ++t)
#pragma unroll
        for (int n = 0; n < 4; ++n)
#pragma unroll
            for (int r = 0; r < 4; ++r) acc[t][n][r] = 0.f;

    uint4 Bc[4];
#pragma unroll
    for (int nt = 0; nt < 4; ++nt) Bc[nt] = wq[nt * 32];

#pragma unroll 4
    for (int kc = 0; kc < 72; ++kc) {
        uint4 Bn[4];
        if (kc < 71) {
#pragma unroll
            for (int nt = 0; nt < 4; ++nt) Bn[nt] = wq[(kc + 1) * 128 + nt * 32];
        } else {
#pragma unroll
            for (int nt = 0; nt < 4; ++nt) Bn[nt] = Bc[nt];
        }

        uint32_t Ah[8], Al[8];
#pragma unroll
        for (int dl = 0; dl < 2; ++dl) {
            int d  = 2 * kc + dl;
            int c  = d / 9;
            int r9 = d - 9 * c;
            int kh = r9 / 3;
            int kw = r9 - 3 * kh;
            uint32_t ta = abase + (uint32_t)(c * PHI_C + kh * PHI_R + kw * 32);
#pragma unroll
            for (int q = 0; q < 4; ++q) {
                uint32_t ah, al;
                asm("ld.shared.v2.b32 {%0,%1}, [%2];" : "=r"(ah), "=r"(al) : "r"(ta + q * 256));
                int ix = (q >> 1) * 4 + (q & 1) + 2 * dl;
                Ah[ix] = ah; Al[ix] = al;
            }
        }

        // pass-major: same-acc RAW distance = 8 mmas
#pragma unroll
        for (int t = 0; t < 2; ++t)
#pragma unroll
            for (int nt = 0; nt < 4; ++nt)
                mma16816(acc[t][nt], Ah + t * 4, Bc[nt].x, Bc[nt].y);
#pragma unroll
        for (int t = 0; t < 2; ++t)
#pragma unroll
            for (int nt = 0; nt < 4; ++nt)
                mma16816(acc[t][nt], Al + t * 4, Bc[nt].x, Bc[nt].y);
#pragma unroll
        for (int t = 0; t < 2; ++t)
#pragma unroll
            for (int nt = 0; nt < 4; ++nt)
                mma16816(acc[t][nt], Ah + t * 4, Bc[nt].z, Bc[nt].w);

#pragma unroll
        for (int nt = 0; nt < 4; ++nt) Bc[nt] = Bn[nt];
    }

    // ---------------- Stage 4: per-o partial stats from registers ----------
    {
        float S[4][2], Q[4][2];
#pragma unroll
        for (int nt = 0; nt < 4; ++nt)
#pragma unroll
            for (int h = 0; h < 2; ++h) {
                float v0 = acc[0][nt][h],     v1 = acc[0][nt][h + 2];
                float v2 = acc[1][nt][h],     v3 = acc[1][nt][h + 2];
                S[nt][h] = (v0 + v1) + (v2 + v3);
                float q = __fmul_rn(v0, v0);
                q = fmaf(v1, v1, q); q = fmaf(v2, v2, q); q = fmaf(v3, v3, q);
                Q[nt][h] = q;
            }
#pragma unroll
        for (int off = 4; off <= 16; off <<= 1)
#pragma unroll
            for (int nt = 0; nt < 4; ++nt)
#pragma unroll
                for (int h = 0; h < 2; ++h) {
                    S[nt][h] += __shfl_xor_sync(0xFFFFFFFFu, S[nt][h], off);
                    Q[nt][h] += __shfl_xor_sync(0xFFFFFFFFu, Q[nt][h], off);
                }
        if (qr == 0) {
#pragma unroll
            for (int nt = 0; nt < 4; ++nt)
#pragma unroll
                for (int h = 0; h < 2; ++h) {
                    sred[w][nt][h][0][gp] = S[nt][h];
                    sred[w][nt][h][1][gp] = Q[nt][h];
                }
        }
        __syncthreads();
        if (tid < 32) {
            int o = tid;
            int nt = o >> 3, rem = o & 7, gpp = rem >> 1, h = rem & 1;
            float Ss = 0.f, Qq = 0.f;
#pragma unroll
            for (int ww = 0; ww < 8; ++ww) {
                Ss += sred[ww][nt][h][0][gpp];
                Qq += sred[ww][nt][h][1][gpp];
            }
            g_part[o * 128 + cta] = make_float2(Ss, Qq);
        }
    }

    grid_barrier(&g_bar1);

    // ---------------- Stage 5: BN params (deterministic) + apply + store ---
    {
        int o = tid >> 3, j = tid & 7;
        float Ss = 0.f, Qq = 0.f;
#pragma unroll
        for (int i = 0; i < 16; ++i) {
            float2 pq = g_part[o * 128 + j * 16 + i];
            Ss += pq.x; Qq += pq.y;
        }
#pragma unroll
        for (int off = 1; off <= 4; off <<= 1) {
            Ss += __shfl_xor_sync(0xFFFFFFFFu, Ss, off);
            Qq += __shfl_xor_sync(0xFFFFFFFFu, Qq, off);
        }
        if (j == 0) {
            float mean = Ss * (1.f / 32768.f);
            float var  = Qq * (1.f / 32768.f) - mean * mean;
            float sc = gamma[o] * rsqrtf(var + 1e-5f);
            bnp[o] = make_float2(sc, fmaf(-mean, sc, beta[o]));
        }
    }
    __syncthreads();

    {
        float* ob = out + ((size_t)b << 17) + (size_t)(r0 + prow) * 64;
#pragma unroll
        for (int t = 0; t < 2; ++t) {
            int col0 = pc + (t << 4) + qr;
#pragma unroll
            for (int nt = 0; nt < 4; ++nt) {
                int o0 = nt * 8 + (gp << 1);
                float2 n0 = bnp[o0];
                float2 n1 = bnp[o0 + 1];
                float* p0 = ob + ((size_t)o0 << 12);
                p0[col0]            = fmaf(acc[t][nt][0], n0.x, n0.y);
                p0[4096 + col0]     = fmaf(acc[t][nt][1], n1.x, n1.y);
                p0[col0 + 8]        = fmaf(acc[t][nt][2], n0.x, n0.y);
                p0[4096 + col0 + 8] = fmaf(acc[t][nt][3], n1.x, n1.y);
            }
        }
    }
}

// ---------------------------------------------------------------------------
extern "C" void kernel_launch(void* const* d_in, const int* in_sizes, int n_in,
                              void* d_out, int out_size) {
    const float* x     = (const float*)d_in[0];
    const float* W     = (const float*)d_in[1];
    const float* gamma = (const float*)d_in[2];
    const float* beta  = (const float*)d_in[3];
    float* out = (float*)d_out;

    cudaFuncSetAttribute(kan_fused, cudaFuncAttributeMaxDynamicSharedMemorySize, SMEM_PHI);
    kan_fused<<<128, 256, SMEM_PHI>>>(x, W, gamma, beta, out);
}

// round 6
// speedup vs baseline: 1.2083x; 1.2083x over previous
#include <cuda_runtime.h>
#include <cuda_bf16.h>
#include <cstdint>

// Problem: B=8, C=16, H=W=64, O=32, K=3, S=1, P=1, G=8, D=144, Kdim=1152
// basis(v,g) = exp(-((v-grid_g)/h)^2) = ex2(-u^2), u = v*C1 + C2[g]
#define C1F 2.1019642153762872f

__device__ __constant__ float C2F[8] = {
     4.2039284307525744f,  3.0028060219661250f,  1.8016836131796750f,  0.6005612043932250f,
    -0.6005612043932250f, -1.8016836131796750f, -3.0028060219661250f, -4.2039284307525744f
};

// Device scratch (no allocation allowed)
__device__ __align__(16) unsigned char g_Wfrag[147456];   // bf16 hi/lo B fragments
__device__ __align__(16) float2 g_part[32 * 128];         // per-(o, cta) sum/sumsq
__device__ unsigned g_bar0 = 0, g_bar1 = 0;               // monotone barrier counters

// ---------------------------------------------------------------------------
// helpers
// ---------------------------------------------------------------------------
__device__ __forceinline__ float ex2f(float m) {
    float r; asm("ex2.approx.f32 %0, %1;" : "=f"(r) : "f"(m)); return r;
}
__device__ __forceinline__ uint32_t pack_hi(float b0, float b1) {
    uint32_t r, u0 = __float_as_uint(b0), u1 = __float_as_uint(b1);
    asm("prmt.b32 %0, %1, %2, 0x7632;" : "=r"(r) : "r"(u0), "r"(u1));
    return r;
}
__device__ __forceinline__ uint32_t pack_lo(float b0, float b1) {
    float l0 = b0 - __uint_as_float(__float_as_uint(b0) & 0xFFFF0000u);
    float l1 = b1 - __uint_as_float(__float_as_uint(b1) & 0xFFFF0000u);
    uint32_t r;
    asm("cvt.rn.bf16x2.f32 %0, %1, %2;" : "=r"(r) : "f"(l1), "f"(l0));
    return r;
}
__device__ __forceinline__ void mma16816(float* c, const uint32_t* a, uint32_t b0, uint32_t b1) {
    asm volatile(
        "mma.sync.aligned.m16n8k16.row.col.f32.bf16.bf16.f32 "
        "{%0,%1,%2,%3}, {%4,%5,%6,%7}, {%8,%9}, {%0,%1,%2,%3};"
        : "+f"(c[0]), "+f"(c[1]), "+f"(c[2]), "+f"(c[3])
        : "r"(a[0]), "r"(a[1]), "r"(a[2]), "r"(a[3]), "r"(b0), "r"(b1));
}
__device__ __forceinline__ uint32_t smem_u32(const void* p) {
    uint32_t a;
    asm("{ .reg .u64 t; cvta.to.shared.u64 t, %1; cvt.u32.u64 %0, t; }" : "=r"(a) : "l"(p));
    return a;
}
// Load Ah/Al for one d-value (4 pixel quads) from Phi tile. half = 2*dl.
__device__ __forceinline__ void lds_A(uint32_t ta, uint32_t* Ah, uint32_t* Al, int half) {
    uint32_t h0, l0, h1, l1, h2, l2, h3, l3;
    asm("ld.shared.v2.b32 {%0,%1}, [%8];\n\t"
        "ld.shared.v2.b32 {%2,%3}, [%8+256];\n\t"
        "ld.shared.v2.b32 {%4,%5}, [%8+512];\n\t"
        "ld.shared.v2.b32 {%6,%7}, [%8+768];"
        : "=r"(h0), "=r"(l0), "=r"(h1), "=r"(l1),
          "=r"(h2), "=r"(l2), "=r"(h3), "=r"(l3)
        : "r"(ta));
    Ah[0 + half] = h0; Al[0 + half] = l0;   // q0
    Ah[1 + half] = h1; Al[1 + half] = l1;   // q1
    Ah[4 + half] = h2; Al[4 + half] = l2;   // q2
    Ah[5 + half] = h3; Al[5 + half] = l3;   // q3
}

// Grid barrier over exactly 128 co-resident CTAs. Monotone counter (graph-safe).
__device__ __forceinline__ void grid_barrier(unsigned* ctr) {
    __threadfence();
    __syncthreads();
    if (threadIdx.x == 0) {
        unsigned prev = atomicAdd(ctr, 1u);
        unsigned target = ((prev >> 7) + 1u) << 7;
        unsigned v;
        do {
            asm volatile("ld.acquire.gpu.global.u32 %0, [%1];" : "=r"(v) : "l"(ctr));
        } while ((int)(v - target) < 0);
    }
    __syncthreads();
}

// ---------------------------------------------------------------------------
// Single fused kernel. 128 CTAs x 256 thr, 1 CTA/SM.
// ---------------------------------------------------------------------------
#define PHI_R 2112                      // 66 * 32 bytes
#define PHI_C 12672                     // 6 * PHI_R
#define OFF_TAB 202752                  // 16 * PHI_C
#define SMEM_TOT (202752 + 640)         // + 80-entry uint2 offset table

__global__ void __launch_bounds__(256, 1) kan_fused(
    const float* __restrict__ x, const float* __restrict__ W,
    const float* __restrict__ gamma, const float* __restrict__ beta,
    float* __restrict__ out)
{
    extern __shared__ char smem[];
    __shared__ float sred[8][4][2][2][4];   // [warp][nt][h][S/Q][gp]
    __shared__ float2 bnp[32];

    const uint32_t sb = smem_u32(smem);
    const int tid = threadIdx.x;
    const int cta = blockIdx.x;
    const int b   = cta >> 4;
    const int r0  = (cta & 15) << 2;

    // ---------------- Stage 1: Wsum slice (o fixed, 288 k-values) ----------
    {
        const int o  = cta >> 2;
        const int k0 = (cta & 3) * 288;
#pragma unroll 1
        for (int i = tid; i < 288; i += 256) {
            const int k = k0 + i;
            const float* p = W + (size_t)o * 165888 + k;
            float a0 = 0.f, a1 = 0.f, a2 = 0.f, a3 = 0.f;
#pragma unroll
            for (int d = 0; d < 144; d += 4) {
                a0 += p[(d + 0) * 1152];
                a1 += p[(d + 1) * 1152];
                a2 += p[(d + 2) * 1152];
                a3 += p[(d + 3) * 1152];
            }
            float s = (a0 + a1) + (a2 + a3);

            uint32_t sbits = __float_as_uint(s);
            unsigned short hib = (unsigned short)(sbits >> 16);
            float hif = __uint_as_float(sbits & 0xFFFF0000u);
            __nv_bfloat16 lo = __float2bfloat16(s - hif);

            int kc   = k >> 4;
            int kl   = k & 15;
            int slot = kl >> 1;
            int hi4  = slot >> 2;
            int s2   = slot & 3;
            int half = kl & 1;
            int base = kc * 2048 + o * 64 + s2 * 16;
            *(unsigned short*)(g_Wfrag + base + hi4 * 4 + half * 2)     = hib;
            *(unsigned short*)(g_Wfrag + base + 8 + hi4 * 4 + half * 2) = *(unsigned short*)&lo;
        }
    }

    // ---------------- Stage 2: Phi tile + A-offset table --------------------
#pragma unroll 1
    for (int idx = tid; idx < 6336; idx += 256) {
        int c   = idx / 396;
        int rem = idx - c * 396;
        int r   = rem / 66;
        int col = rem - r * 66;
        int y  = r0 - 1 + r;
        int xx = col - 1;
        float v = 0.f;
        if ((unsigned)y < 64u && (unsigned)xx < 64u)
            v = x[(((b * 16 + c) << 6) + y) * 64 + xx];
        float bb[8];
#pragma unroll
        for (int g = 0; g < 8; ++g) {
            float u = fmaf(v, C1F, C2F[g]);
            bb[g] = ex2f(__fmul_rn(u, -u));
        }
        uint32_t hw[4], lw[4];
#pragma unroll
        for (int i = 0; i < 4; ++i) {
            hw[i] = pack_hi(bb[2 * i], bb[2 * i + 1]);
            lw[i] = pack_lo(bb[2 * i], bb[2 * i + 1]);
        }
        uint32_t a = sb + c * PHI_C + r * PHI_R + col * 32;
        asm volatile("st.shared.v4.b32 [%0], {%1,%2,%3,%4};"
                     :: "r"(a), "r"(hw[0]), "r"(lw[0]), "r"(hw[1]), "r"(lw[1]) : "memory");
        asm volatile("st.shared.v4.b32 [%0+16], {%1,%2,%3,%4};"
                     :: "r"(a), "r"(hw[2]), "r"(lw[2]), "r"(hw[3]), "r"(lw[3]) : "memory");
    }
    // chunk -> Phi byte-offset pairs (d0 = 2*kc, d1 = 2*kc+1); padded to 80
    if (tid < 80) {
        uint2 e = make_uint2(0u, 0u);
        if (tid < 72) {
            int d0 = 2 * tid, d1 = 2 * tid + 1;
            int c0 = d0 / 9, r90 = d0 - 9 * c0;
            int c1 = d1 / 9, r91 = d1 - 9 * c1;
            e.x = (uint32_t)(c0 * PHI_C + (r90 / 3) * PHI_R + (r90 % 3) * 32);
            e.y = (uint32_t)(c1 * PHI_C + (r91 / 3) * PHI_R + (r91 % 3) * 32);
        }
        ((uint2*)(smem + OFF_TAB))[tid] = e;
    }

    grid_barrier(&g_bar0);    // Wfrag globally ready; Phi + table smem ready

    // ---------------- Stage 3: mma mainloop --------------------------------
    const int lane = tid & 31;
    const int w    = tid >> 5;
    const int prow = w >> 1;
    const int pc   = (w & 1) << 5;
    const int qr   = lane >> 2;
    const int gp   = lane & 3;

    const uint32_t abase = sb + (uint32_t)prow * PHI_R + (uint32_t)(pc + qr) * 32 + (uint32_t)gp * 8;
    const uint4* wq = ((const uint4*)g_Wfrag) + lane;
    const uint2* offT = (const uint2*)(smem + OFF_TAB);

    float acc[2][4][4];
#pragma unroll
    for (int t = 0; t < 2; ++t)
#pragma unroll
        for (int n = 0; n < 4; ++n)
#pragma unroll
            for (int r = 0; r < 4; ++r) acc[t][n][r] = 0.f;

    // A double-buffer: chunk kc lives in buffer (kc & 1)
    uint32_t Ahb[2][8], Alb[2][8];
    {
        uint2 o0 = offT[0];
        lds_A(abase + o0.x, Ahb[0], Alb[0], 0);
        lds_A(abase + o0.y, Ahb[0], Alb[0], 2);
    }
    uint2 offn = offT[1];

    // B ring: 4 chunks prefetched in registers
    uint4 Bb[4][4];
#pragma unroll
    for (int j = 0; j < 4; ++j)
#pragma unroll
        for (int nt = 0; nt < 4; ++nt)
            Bb[j][nt] = wq[j * 128 + nt * 32];

#pragma unroll 1
    for (int kc4 = 0; kc4 < 72; kc4 += 4) {
#pragma unroll
        for (int j = 0; j < 4; ++j) {
            const int kc  = kc4 + j;
            const int cur = j & 1;
            const int nxt = cur ^ 1;

            // A prefetch for chunk kc+1
            if (kc < 71) {
                lds_A(abase + offn.x, Ahb[nxt], Alb[nxt], 0);
                lds_A(abase + offn.y, Ahb[nxt], Alb[nxt], 2);
            }
            offn = offT[kc + 2];   // table padded; always safe

            // 24 mma, pass-major (same-acc RAW distance 8)
#pragma unroll
            for (int t = 0; t < 2; ++t)
#pragma unroll
                for (int nt = 0; nt < 4; ++nt)
                    mma16816(acc[t][nt], Ahb[cur] + t * 4, Bb[j][nt].x, Bb[j][nt].y);
#pragma unroll
            for (int t = 0; t < 2; ++t)
#pragma unroll
                for (int nt = 0; nt < 4; ++nt)
                    mma16816(acc[t][nt], Alb[cur] + t * 4, Bb[j][nt].x, Bb[j][nt].y);
#pragma unroll
            for (int t = 0; t < 2; ++t)
#pragma unroll
                for (int nt = 0; nt < 4; ++nt)
                    mma16816(acc[t][nt], Ahb[cur] + t * 4, Bb[j][nt].z, Bb[j][nt].w);

            // B prefetch for chunk kc+4 (reuses slot j)
            if (kc < 68) {
#pragma unroll
                for (int nt = 0; nt < 4; ++nt)
                    Bb[j][nt] = wq[(kc + 4) * 128 + nt * 32];
            }
        }
    }

    // ---------------- Stage 4: per-o partial stats from registers ----------
    {
        float S[4][2], Q[4][2];
#pragma unroll
        for (int nt = 0; nt < 4; ++nt)
#pragma unroll
            for (int h = 0; h < 2; ++h) {
                float v0 = acc[0][nt][h],     v1 = acc[0][nt][h + 2];
                float v2 = acc[1][nt][h],     v3 = acc[1][nt][h + 2];
                S[nt][h] = (v0 + v1) + (v2 + v3);
                float q = __fmul_rn(v0, v0);
                q = fmaf(v1, v1, q); q = fmaf(v2, v2, q); q = fmaf(v3, v3, q);
                Q[nt][h] = q;
            }
#pragma unroll
        for (int off = 4; off <= 16; off <<= 1)
#pragma unroll
            for (int nt = 0; nt < 4; ++nt)
#pragma unroll
                for (int h = 0; h < 2; ++h) {
                    S[nt][h] += __shfl_xor_sync(0xFFFFFFFFu, S[nt][h], off);
                    Q[nt][h] += __shfl_xor_sync(0xFFFFFFFFu, Q[nt][h], off);
                }
        if (qr == 0) {
#pragma unroll
            for (int nt = 0; nt < 4; ++nt)
#pragma unroll
                for (int h = 0; h < 2; ++h) {
                    sred[w][nt][h][0][gp] = S[nt][h];
                    sred[w][nt][h][1][gp] = Q[nt][h];
                }
        }
        __syncthreads();
        if (tid < 32) {
            int o = tid;
            int nt = o >> 3, rem = o & 7, gpp = rem >> 1, h = rem & 1;
            float Ss = 0.f, Qq = 0.f;
#pragma unroll
            for (int ww = 0; ww < 8; ++ww) {
                Ss += sred[ww][nt][h][0][gpp];
                Qq += sred[ww][nt][h][1][gpp];
            }
            g_part[o * 128 + cta] = make_float2(Ss, Qq);
        }
    }

    grid_barrier(&g_bar1);

    // ---------------- Stage 5: BN params (deterministic) + apply + store ---
    {
        int o = tid >> 3, j = tid & 7;
        float Ss = 0.f, Qq = 0.f;
#pragma unroll
        for (int i = 0; i < 16; ++i) {
            float2 pq = g_part[o * 128 + j * 16 + i];
            Ss += pq.x; Qq += pq.y;
        }
#pragma unroll
        for (int off = 1; off <= 4; off <<= 1) {
            Ss += __shfl_xor_sync(0xFFFFFFFFu, Ss, off);
            Qq += __shfl_xor_sync(0xFFFFFFFFu, Qq, off);
        }
        if (j == 0) {
            float mean = Ss * (1.f / 32768.f);
            float var  = Qq * (1.f / 32768.f) - mean * mean;
            float sc = gamma[o] * rsqrtf(var + 1e-5f);
            bnp[o] = make_float2(sc, fmaf(-mean, sc, beta[o]));
        }
    }
    __syncthreads();

    {
        float* ob = out + ((size_t)b << 17) + (size_t)(r0 + prow) * 64;
#pragma unroll
        for (int t = 0; t < 2; ++t) {
            int col0 = pc + (t << 4) + qr;
#pragma unroll
            for (int nt = 0; nt < 4; ++nt) {
                int o0 = nt * 8 + (gp << 1);
                float2 n0 = bnp[o0];
                float2 n1 = bnp[o0 + 1];
                float* p0 = ob + ((size_t)o0 << 12);
                p0[col0]            = fmaf(acc[t][nt][0], n0.x, n0.y);
                p0[4096 + col0]     = fmaf(acc[t][nt][1], n1.x, n1.y);
                p0[col0 + 8]        = fmaf(acc[t][nt][2], n0.x, n0.y);
                p0[4096 + col0 + 8] = fmaf(acc[t][nt][3], n1.x, n1.y);
            }
        }
    }
}

// ---------------------------------------------------------------------------
extern "C" void kernel_launch(void* const* d_in, const int* in_sizes, int n_in,
                              void* d_out, int out_size) {
    const float* x     = (const float*)d_in[0];
    const float* W     = (const float*)d_in[1];
    const float* gamma = (const float*)d_in[2];
    const float* beta  = (const float*)d_in[3];
    float* out = (float*)d_out;

    cudaFuncSetAttribute(kan_fused, cudaFuncAttributeMaxDynamicSharedMemorySize, SMEM_TOT);
    kan_fused<<<128, 256, SMEM_TOT>>>(x, W, gamma, beta, out);
}

// round 7
// speedup vs baseline: 1.2388x; 1.0253x over previous
#include <cuda_runtime.h>
#include <cuda_bf16.h>
#include <cstdint>

// Problem: B=8, C=16, H=W=64, O=32, K=3, S=1, P=1, G=8, D=144, Kdim=1152
// basis(v,g) = exp(-((v-grid_g)/h)^2) = ex2(-u^2), u = v*C1 + C2[g]
#define C1F 2.1019642153762872f

__device__ __constant__ float C2F[8] = {
     4.2039284307525744f,  3.0028060219661250f,  1.8016836131796750f,  0.6005612043932250f,
    -0.6005612043932250f, -1.8016836131796750f, -3.0028060219661250f, -4.2039284307525744f
};

// Device scratch (no allocation allowed)
__device__ __align__(16) unsigned char g_Wfrag[147456];   // bf16 hi/lo B fragments
__device__ __align__(16) float2 g_part[32 * 128];         // per-(o, cta) sum/sumsq
__device__ unsigned g_bar0 = 0, g_bar1 = 0;               // monotone barrier counters

// ---------------------------------------------------------------------------
// helpers
// ---------------------------------------------------------------------------
__device__ __forceinline__ float ex2f(float m) {
    float r; asm("ex2.approx.f32 %0, %1;" : "=f"(r) : "f"(m)); return r;
}
__device__ __forceinline__ uint32_t pack_hi(float b0, float b1) {
    uint32_t r, u0 = __float_as_uint(b0), u1 = __float_as_uint(b1);
    asm("prmt.b32 %0, %1, %2, 0x7632;" : "=r"(r) : "r"(u0), "r"(u1));
    return r;
}
__device__ __forceinline__ uint32_t pack_lo(float b0, float b1) {
    float l0 = b0 - __uint_as_float(__float_as_uint(b0) & 0xFFFF0000u);
    float l1 = b1 - __uint_as_float(__float_as_uint(b1) & 0xFFFF0000u);
    uint32_t r;
    asm("cvt.rn.bf16x2.f32 %0, %1, %2;" : "=r"(r) : "f"(l1), "f"(l0));
    return r;
}
__device__ __forceinline__ void mma16816(float* c, const uint32_t* a, uint32_t b0, uint32_t b1) {
    asm volatile(
        "mma.sync.aligned.m16n8k16.row.col.f32.bf16.bf16.f32 "
        "{%0,%1,%2,%3}, {%4,%5,%6,%7}, {%8,%9}, {%0,%1,%2,%3};"
        : "+f"(c[0]), "+f"(c[1]), "+f"(c[2]), "+f"(c[3])
        : "r"(a[0]), "r"(a[1]), "r"(a[2]), "r"(a[3]), "r"(b0), "r"(b1));
}
__device__ __forceinline__ uint32_t smem_u32(const void* p) {
    uint32_t a;
    asm("{ .reg .u64 t; cvta.to.shared.u64 t, %1; cvt.u32.u64 %0, t; }" : "=r"(a) : "l"(p));
    return a;
}
// Load Ah/Al for one d-value (4 pixel quads) from Phi tile. half = 2*dl.
__device__ __forceinline__ void lds_A(uint32_t ta, uint32_t* Ah, uint32_t* Al, int half) {
    uint32_t h0, l0, h1, l1, h2, l2, h3, l3;
    asm("ld.shared.v2.b32 {%0,%1}, [%8];\n\t"
        "ld.shared.v2.b32 {%2,%3}, [%8+256];\n\t"
        "ld.shared.v2.b32 {%4,%5}, [%8+512];\n\t"
        "ld.shared.v2.b32 {%6,%7}, [%8+768];"
        : "=r"(h0), "=r"(l0), "=r"(h1), "=r"(l1),
          "=r"(h2), "=r"(l2), "=r"(h3), "=r"(l3)
        : "r"(ta));
    Ah[0 + half] = h0; Al[0 + half] = l0;   // q0
    Ah[1 + half] = h1; Al[1 + half] = l1;   // q1
    Ah[4 + half] = h2; Al[4 + half] = l2;   // q2
    Ah[5 + half] = h3; Al[5 + half] = l3;   // q3
}

// Grid barrier over exactly 128 co-resident CTAs. Monotone counter (graph-safe).
__device__ __forceinline__ void grid_barrier(unsigned* ctr) {
    __threadfence();
    __syncthreads();
    if (threadIdx.x == 0) {
        unsigned prev = atomicAdd(ctr, 1u);
        unsigned target = ((prev >> 7) + 1u) << 7;
        unsigned v;
        do {
            asm volatile("ld.acquire.gpu.global.u32 %0, [%1];" : "=r"(v) : "l"(ctr));
        } while ((int)(v - target) < 0);
    }
    __syncthreads();
}

// ---------------------------------------------------------------------------
// Single fused kernel. 128 CTAs x 512 thr (16 warps), 1 CTA/SM.
// Warps 0-7: o in [0,16); warps 8-15: same pixels, o in [16,32).
// ---------------------------------------------------------------------------
#define PHI_R 2112                      // 66 * 32 bytes
#define PHI_C 12672                     // 6 * PHI_R
#define OFF_TAB 202752                  // 16 * PHI_C
#define SMEM_TOT (202752 + 640)         // + 80-entry uint2 offset table

__global__ void __launch_bounds__(512, 1) kan_fused(
    const float* __restrict__ x, const float* __restrict__ W,
    const float* __restrict__ gamma, const float* __restrict__ beta,
    float* __restrict__ out)
{
    extern __shared__ char smem[];
    __shared__ float sred[16][2][2][2][4];  // [warp][ntl][h][S/Q][gp]
    __shared__ float2 bnp[32];

    const uint32_t sb = smem_u32(smem);
    const int tid = threadIdx.x;
    const int cta = blockIdx.x;
    const int b   = cta >> 4;
    const int r0  = (cta & 15) << 2;

    // ---------------- Stage 1: Wsum slice (o fixed, 288 k-values) ----------
    {
        const int o  = cta >> 2;
        const int k0 = (cta & 3) * 288;
#pragma unroll 1
        for (int i = tid; i < 288; i += 512) {
            const int k = k0 + i;
            const float* p = W + (size_t)o * 165888 + k;
            float a0 = 0.f, a1 = 0.f, a2 = 0.f, a3 = 0.f;
#pragma unroll
            for (int d = 0; d < 144; d += 4) {
                a0 += p[(d + 0) * 1152];
                a1 += p[(d + 1) * 1152];
                a2 += p[(d + 2) * 1152];
                a3 += p[(d + 3) * 1152];
            }
            float s = (a0 + a1) + (a2 + a3);

            uint32_t sbits = __float_as_uint(s);
            unsigned short hib = (unsigned short)(sbits >> 16);
            float hif = __uint_as_float(sbits & 0xFFFF0000u);
            __nv_bfloat16 lo = __float2bfloat16(s - hif);

            int kc   = k >> 4;
            int kl   = k & 15;
            int slot = kl >> 1;
            int hi4  = slot >> 2;
            int s2   = slot & 3;
            int half = kl & 1;
            int base = kc * 2048 + o * 64 + s2 * 16;
            *(unsigned short*)(g_Wfrag + base + hi4 * 4 + half * 2)     = hib;
            *(unsigned short*)(g_Wfrag + base + 8 + hi4 * 4 + half * 2) = *(unsigned short*)&lo;
        }
    }

    // ---------------- Stage 2: Phi tile + A-offset table --------------------
#pragma unroll 1
    for (int idx = tid; idx < 6336; idx += 512) {
        int c   = idx / 396;
        int rem = idx - c * 396;
        int r   = rem / 66;
        int col = rem - r * 66;
        int y  = r0 - 1 + r;
        int xx = col - 1;
        float v = 0.f;
        if ((unsigned)y < 64u && (unsigned)xx < 64u)
            v = x[(((b * 16 + c) << 6) + y) * 64 + xx];
        float bb[8];
#pragma unroll
        for (int g = 0; g < 8; ++g) {
            float u = fmaf(v, C1F, C2F[g]);
            bb[g] = ex2f(__fmul_rn(u, -u));
        }
        uint32_t hw[4], lw[4];
#pragma unroll
        for (int i = 0; i < 4; ++i) {
            hw[i] = pack_hi(bb[2 * i], bb[2 * i + 1]);
            lw[i] = pack_lo(bb[2 * i], bb[2 * i + 1]);
        }
        uint32_t a = sb + c * PHI_C + r * PHI_R + col * 32;
        asm volatile("st.shared.v4.b32 [%0], {%1,%2,%3,%4};"
                     :: "r"(a), "r"(hw[0]), "r"(lw[0]), "r"(hw[1]), "r"(lw[1]) : "memory");
        asm volatile("st.shared.v4.b32 [%0+16], {%1,%2,%3,%4};"
                     :: "r"(a), "r"(hw[2]), "r"(lw[2]), "r"(hw[3]), "r"(lw[3]) : "memory");
    }
    // chunk -> Phi byte-offset pairs (d0 = 2*kc, d1 = 2*kc+1); padded to 80
    if (tid < 80) {
        uint2 e = make_uint2(0u, 0u);
        if (tid < 72) {
            int d0 = 2 * tid, d1 = 2 * tid + 1;
            int c0 = d0 / 9, r90 = d0 - 9 * c0;
            int c1 = d1 / 9, r91 = d1 - 9 * c1;
            e.x = (uint32_t)(c0 * PHI_C + (r90 / 3) * PHI_R + (r90 % 3) * 32);
            e.y = (uint32_t)(c1 * PHI_C + (r91 / 3) * PHI_R + (r91 % 3) * 32);
        }
        ((uint2*)(smem + OFF_TAB))[tid] = e;
    }

    grid_barrier(&g_bar0);    // Wfrag globally ready; Phi + table smem ready

    // ---------------- Stage 3: mma mainloop --------------------------------
    const int lane = tid & 31;
    const int w    = tid >> 5;              // 0..15
    const int wh   = w >> 3;                // warp half: nt base = wh*2
    const int wp   = w & 7;                 // pixel-tile warp id
    const int prow = wp >> 1;
    const int pc   = (wp & 1) << 5;
    const int qr   = lane >> 2;
    const int gp   = lane & 3;

    const uint32_t abase = sb + (uint32_t)prow * PHI_R + (uint32_t)(pc + qr) * 32 + (uint32_t)gp * 8;
    const uint4* wq = ((const uint4*)g_Wfrag) + lane + (wh ? 64 : 0);  // nt base offset (2*32)
    const uint2* offT = (const uint2*)(smem + OFF_TAB);

    float acc[2][2][4];
#pragma unroll
    for (int t = 0; t < 2; ++t)
#pragma unroll
        for (int n = 0; n < 2; ++n)
#pragma unroll
            for (int r = 0; r < 4; ++r) acc[t][n][r] = 0.f;

    // A double-buffer: chunk kc lives in buffer (kc & 1)
    uint32_t Ahb[2][8], Alb[2][8];
    {
        uint2 o0 = offT[0];
        lds_A(abase + o0.x, Ahb[0], Alb[0], 0);
        lds_A(abase + o0.y, Ahb[0], Alb[0], 2);
    }
    uint2 offn = offT[1];

    // B ring: 4 chunks x 2 local nt in registers
    uint4 Bb[4][2];
#pragma unroll
    for (int j = 0; j < 4; ++j)
#pragma unroll
        for (int nl = 0; nl < 2; ++nl)
            Bb[j][nl] = wq[j * 128 + nl * 32];

#pragma unroll 1
    for (int kc4 = 0; kc4 < 72; kc4 += 4) {
#pragma unroll
        for (int j = 0; j < 4; ++j) {
            const int kc  = kc4 + j;
            const int cur = j & 1;
            const int nxt = cur ^ 1;

            // A prefetch for chunk kc+1
            if (kc < 71) {
                lds_A(abase + offn.x, Ahb[nxt], Alb[nxt], 0);
                lds_A(abase + offn.y, Ahb[nxt], Alb[nxt], 2);
            }
            offn = offT[kc + 2];   // table padded; always safe

            // 12 mma, pass-major (same-acc RAW distance 4)
#pragma unroll
            for (int t = 0; t < 2; ++t)
#pragma unroll
                for (int nl = 0; nl < 2; ++nl)
                    mma16816(acc[t][nl], Ahb[cur] + t * 4, Bb[j][nl].x, Bb[j][nl].y);
#pragma unroll
            for (int t = 0; t < 2; ++t)
#pragma unroll
                for (int nl = 0; nl < 2; ++nl)
                    mma16816(acc[t][nl], Alb[cur] + t * 4, Bb[j][nl].x, Bb[j][nl].y);
#pragma unroll
            for (int t = 0; t < 2; ++t)
#pragma unroll
                for (int nl = 0; nl < 2; ++nl)
                    mma16816(acc[t][nl], Ahb[cur] + t * 4, Bb[j][nl].z, Bb[j][nl].w);

            // B prefetch for chunk kc+4 (reuses slot j)
            if (kc < 68) {
#pragma unroll
                for (int nl = 0; nl < 2; ++nl)
                    Bb[j][nl] = wq[(kc + 4) * 128 + nl * 32];
            }
        }
    }

    // ---------------- Stage 4: per-o partial stats from registers ----------
    {
        float S[2][2], Q[2][2];
#pragma unroll
        for (int nl = 0; nl < 2; ++nl)
#pragma unroll
            for (int h = 0; h < 2; ++h) {
                float v0 = acc[0][nl][h],     v1 = acc[0][nl][h + 2];
                float v2 = acc[1][nl][h],     v3 = acc[1][nl][h + 2];
                S[nl][h] = (v0 + v1) + (v2 + v3);
                float q = __fmul_rn(v0, v0);
                q = fmaf(v1, v1, q); q = fmaf(v2, v2, q); q = fmaf(v3, v3, q);
                Q[nl][h] = q;
            }
#pragma unroll
        for (int off = 4; off <= 16; off <<= 1)
#pragma unroll
            for (int nl = 0; nl < 2; ++nl)
#pragma unroll
                for (int h = 0; h < 2; ++h) {
                    S[nl][h] += __shfl_xor_sync(0xFFFFFFFFu, S[nl][h], off);
                    Q[nl][h] += __shfl_xor_sync(0xFFFFFFFFu, Q[nl][h], off);
                }
        if (qr == 0) {
#pragma unroll
            for (int nl = 0; nl < 2; ++nl)
#pragma unroll
                for (int h = 0; h < 2; ++h) {
                    sred[w][nl][h][0][gp] = S[nl][h];
                    sred[w][nl][h][1][gp] = Q[nl][h];
                }
        }
        __syncthreads();
        if (tid < 32) {
            int o = tid;
            int nt = o >> 3, rem = o & 7, gpp = rem >> 1, h = rem & 1;
            int whalf = nt >> 1, ntl = nt & 1;
            float Ss = 0.f, Qq = 0.f;
#pragma unroll
            for (int ww = 0; ww < 8; ++ww) {
                Ss += sred[whalf * 8 + ww][ntl][h][0][gpp];
                Qq += sred[whalf * 8 + ww][ntl][h][1][gpp];
            }
            g_part[o * 128 + cta] = make_float2(Ss, Qq);
        }
    }

    grid_barrier(&g_bar1);

    // ---------------- Stage 5: BN params (deterministic) + apply + store ---
    if (tid < 256) {
        int o = tid >> 3, j = tid & 7;
        float Ss = 0.f, Qq = 0.f;
#pragma unroll
        for (int i = 0; i < 16; ++i) {
            float2 pq = g_part[o * 128 + j * 16 + i];
            Ss += pq.x; Qq += pq.y;
        }
#pragma unroll
        for (int off = 1; off <= 4; off <<= 1) {
            Ss += __shfl_xor_sync(0xFFFFFFFFu, Ss, off);
            Qq += __shfl_xor_sync(0xFFFFFFFFu, Qq, off);
        }
        if (j == 0) {
            float mean = Ss * (1.f / 32768.f);
            float var  = Qq * (1.f / 32768.f) - mean * mean;
            float sc = gamma[o] * rsqrtf(var + 1e-5f);
            bnp[o] = make_float2(sc, fmaf(-mean, sc, beta[o]));
        }
    }
    __syncthreads();

    {
        float* ob = out + ((size_t)b << 17) + (size_t)(r0 + prow) * 64;
#pragma unroll
        for (int t = 0; t < 2; ++t) {
            int col0 = pc + (t << 4) + qr;
#pragma unroll
            for (int nl = 0; nl < 2; ++nl) {
                int o0 = (wh * 2 + nl) * 8 + (gp << 1);
                float2 n0 = bnp[o0];
                float2 n1 = bnp[o0 + 1];
                float* p0 = ob + ((size_t)o0 << 12);
                p0[col0]            = fmaf(acc[t][nl][0], n0.x, n0.y);
                p0[4096 + col0]     = fmaf(acc[t][nl][1], n1.x, n1.y);
                p0[col0 + 8]        = fmaf(acc[t][nl][2], n0.x, n0.y);
                p0[4096 + col0 + 8] = fmaf(acc[t][nl][3], n1.x, n1.y);
            }
        }
    }
}

// ---------------------------------------------------------------------------
extern "C" void kernel_launch(void* const* d_in, const int* in_sizes, int n_in,
                              void* d_out, int out_size) {
    const float* x     = (const float*)d_in[0];
    const float* W     = (const float*)d_in[1];
    const float* gamma = (const float*)d_in[2];
    const float* beta  = (const float*)d_in[3];
    float* out = (float*)d_out;

    cudaFuncSetAttribute(kan_fused, cudaFuncAttributeMaxDynamicSharedMemorySize, SMEM_TOT);
    kan_fused<<<128, 512, SMEM_TOT>>>(x, W, gamma, beta, out);
}

// round 8
// speedup vs baseline: 1.2957x; 1.0459x over previous
#include <cuda_runtime.h>
#include <cuda_bf16.h>
#include <cstdint>

// Problem: B=8, C=16, H=W=64, O=32, K=3, S=1, P=1, G=8, D=144, Kdim=1152
// basis(v,g) = exp(-((v-grid_g)/h)^2) = ex2(-u^2), u = v*C1 + C2[g]
#define C1F 2.1019642153762872f

__device__ __constant__ float C2F[8] = {
     4.2039284307525744f,  3.0028060219661250f,  1.8016836131796750f,  0.6005612043932250f,
    -0.6005612043932250f, -1.8016836131796750f, -3.0028060219661250f, -4.2039284307525744f
};

// Device scratch (no allocation allowed)
__device__ __align__(16) unsigned char g_Wfrag[147456];   // bf16 hi/lo B fragments
__device__ __align__(16) float2 g_part[32 * 128];         // per-(o, cta) sum/sumsq
__device__ unsigned g_bar0 = 0, g_bar1 = 0;               // monotone barrier counters

// ---------------------------------------------------------------------------
// helpers
// ---------------------------------------------------------------------------
__device__ __forceinline__ float ex2f(float m) {
    float r; asm("ex2.approx.f32 %0, %1;" : "=f"(r) : "f"(m)); return r;
}
__device__ __forceinline__ uint32_t pack_hi(float b0, float b1) {
    uint32_t r, u0 = __float_as_uint(b0), u1 = __float_as_uint(b1);
    asm("prmt.b32 %0, %1, %2, 0x7632;" : "=r"(r) : "r"(u0), "r"(u1));
    return r;
}
__device__ __forceinline__ uint32_t pack_lo(float b0, float b1) {
    float l0 = b0 - __uint_as_float(__float_as_uint(b0) & 0xFFFF0000u);
    float l1 = b1 - __uint_as_float(__float_as_uint(b1) & 0xFFFF0000u);
    uint32_t r;
    asm("cvt.rn.bf16x2.f32 %0, %1, %2;" : "=r"(r) : "f"(l1), "f"(l0));
    return r;
}
__device__ __forceinline__ void mma16816(float* c, const uint32_t* a, uint32_t b0, uint32_t b1) {
    asm volatile(
        "mma.sync.aligned.m16n8k16.row.col.f32.bf16.bf16.f32 "
        "{%0,%1,%2,%3}, {%4,%5,%6,%7}, {%8,%9}, {%0,%1,%2,%3};"
        : "+f"(c[0]), "+f"(c[1]), "+f"(c[2]), "+f"(c[3])
        : "r"(a[0]), "r"(a[1]), "r"(a[2]), "r"(a[3]), "r"(b0), "r"(b1));
}
__device__ __forceinline__ uint32_t smem_u32(const void* p) {
    uint32_t a;
    asm("{ .reg .u64 t; cvta.to.shared.u64 t, %1; cvt.u32.u64 %0, t; }" : "=r"(a) : "l"(p));
    return a;
}
// Load Ah/Al for one d-value (4 pixel quads) from Phi tile. half = 2*dl.
__device__ __forceinline__ void lds_A(uint32_t ta, uint32_t* Ah, uint32_t* Al, int half) {
    uint32_t h0, l0, h1, l1, h2, l2, h3, l3;
    asm("ld.shared.v2.b32 {%0,%1}, [%8];\n\t"
        "ld.shared.v2.b32 {%2,%3}, [%8+256];\n\t"
        "ld.shared.v2.b32 {%4,%5}, [%8+512];\n\t"
        "ld.shared.v2.b32 {%6,%7}, [%8+768];"
        : "=r"(h0), "=r"(l0), "=r"(h1), "=r"(l1),
          "=r"(h2), "=r"(l2), "=r"(h3), "=r"(l3)
        : "r"(ta));
    Ah[0 + half] = h0; Al[0 + half] = l0;   // q0
    Ah[1 + half] = h1; Al[1 + half] = l1;   // q1
    Ah[4 + half] = h2; Al[4 + half] = l2;   // q2
    Ah[5 + half] = h3; Al[5 + half] = l3;   // q3
}

// Grid barrier over exactly 128 co-resident CTAs. Monotone counter (graph-safe).
__device__ __forceinline__ void grid_barrier(unsigned* ctr) {
    __threadfence();
    __syncthreads();
    if (threadIdx.x == 0) {
        unsigned prev = atomicAdd(ctr, 1u);
        unsigned target = ((prev >> 7) + 1u) << 7;
        unsigned v;
        do {
            asm volatile("ld.acquire.gpu.global.u32 %0, [%1];" : "=r"(v) : "l"(ctr));
        } while ((int)(v - target) < 0);
    }
    __syncthreads();
}

// ---------------------------------------------------------------------------
// Single fused kernel. 128 CTAs x 512 thr (16 warps), 1 CTA/SM.
// Warps 0-7: o in [0,16); warps 8-15: same pixels, o in [16,32).
// Each warp's k-chunk schedule is STAGGERED (start = wp*9 + wh*4, mod 72) to
// break the post-barrier convoy and keep tensor + LSU pipes co-busy.
// ---------------------------------------------------------------------------
#define PHI_R 2112                      // 66 * 32 bytes
#define PHI_C 12672                     // 6 * PHI_R
#define OFF_TAB 202752                  // 16 * PHI_C
#define SMEM_TOT (202752 + 1152)        // + 144-entry uint2 offset table

__global__ void __launch_bounds__(512, 1) kan_fused(
    const float* __restrict__ x, const float* __restrict__ W,
    const float* __restrict__ gamma, const float* __restrict__ beta,
    float* __restrict__ out)
{
    extern __shared__ char smem[];
    __shared__ float sred[16][2][2][2][4];  // [warp][ntl][h][S/Q][gp]
    __shared__ float2 bnp[32];

    const uint32_t sb = smem_u32(smem);
    const int tid = threadIdx.x;
    const int cta = blockIdx.x;
    const int b   = cta >> 4;
    const int r0  = (cta & 15) << 2;

    // ---------------- Stage 1: Wsum slice (o fixed, 288 k-values) ----------
    {
        const int o  = cta >> 2;
        const int k0 = (cta & 3) * 288;
#pragma unroll 1
        for (int i = tid; i < 288; i += 512) {
            const int k = k0 + i;
            const float* p = W + (size_t)o * 165888 + k;
            float a0 = 0.f, a1 = 0.f, a2 = 0.f, a3 = 0.f;
#pragma unroll
            for (int d = 0; d < 144; d += 4) {
                a0 += p[(d + 0) * 1152];
                a1 += p[(d + 1) * 1152];
                a2 += p[(d + 2) * 1152];
                a3 += p[(d + 3) * 1152];
            }
            float s = (a0 + a1) + (a2 + a3);

            uint32_t sbits = __float_as_uint(s);
            unsigned short hib = (unsigned short)(sbits >> 16);
            float hif = __uint_as_float(sbits & 0xFFFF0000u);
            __nv_bfloat16 lo = __float2bfloat16(s - hif);

            int kc   = k >> 4;
            int kl   = k & 15;
            int slot = kl >> 1;
            int hi4  = slot >> 2;
            int s2   = slot & 3;
            int half = kl & 1;
            int base = kc * 2048 + o * 64 + s2 * 16;
            *(unsigned short*)(g_Wfrag + base + hi4 * 4 + half * 2)     = hib;
            *(unsigned short*)(g_Wfrag + base + 8 + hi4 * 4 + half * 2) = *(unsigned short*)&lo;
        }
    }

    // ---------------- Stage 2: Phi tile + A-offset table --------------------
#pragma unroll 1
    for (int idx = tid; idx < 6336; idx += 512) {
        int c   = idx / 396;
        int rem = idx - c * 396;
        int r   = rem / 66;
        int col = rem - r * 66;
        int y  = r0 - 1 + r;
        int xx = col - 1;
        float v = 0.f;
        if ((unsigned)y < 64u && (unsigned)xx < 64u)
            v = x[(((b * 16 + c) << 6) + y) * 64 + xx];
        float bb[8];
#pragma unroll
        for (int g = 0; g < 8; ++g) {
            float u = fmaf(v, C1F, C2F[g]);
            bb[g] = ex2f(__fmul_rn(u, -u));
        }
        uint32_t hw[4], lw[4];
#pragma unroll
        for (int i = 0; i < 4; ++i) {
            hw[i] = pack_hi(bb[2 * i], bb[2 * i + 1]);
            lw[i] = pack_lo(bb[2 * i], bb[2 * i + 1]);
        }
        uint32_t a = sb + c * PHI_C + r * PHI_R + col * 32;
        asm volatile("st.shared.v4.b32 [%0], {%1,%2,%3,%4};"
                     :: "r"(a), "r"(hw[0]), "r"(lw[0]), "r"(hw[1]), "r"(lw[1]) : "memory");
        asm volatile("st.shared.v4.b32 [%0+16], {%1,%2,%3,%4};"
                     :: "r"(a), "r"(hw[2]), "r"(lw[2]), "r"(hw[3]), "r"(lw[3]) : "memory");
    }
    // chunk -> Phi byte-offset pairs, duplicated to 144 entries (wrap-free)
    if (tid < 144) {
        int kc = tid - (tid >= 72 ? 72 : 0);
        int d0 = 2 * kc, d1 = 2 * kc + 1;
        int c0 = d0 / 9, r90 = d0 - 9 * c0;
        int c1 = d1 / 9, r91 = d1 - 9 * c1;
        uint2 e;
        e.x = (uint32_t)(c0 * PHI_C + (r90 / 3) * PHI_R + (r90 % 3) * 32);
        e.y = (uint32_t)(c1 * PHI_C + (r91 / 3) * PHI_R + (r91 % 3) * 32);
        ((uint2*)(smem + OFF_TAB))[tid] = e;
    }

    grid_barrier(&g_bar0);    // Wfrag globally ready; Phi + table smem ready

    // ---------------- Stage 3: mma mainloop (staggered schedule) -----------
    const int lane = tid & 31;
    const int w    = tid >> 5;              // 0..15
    const int wh   = w >> 3;                // warp half: nt base = wh*2
    const int wp   = w & 7;                 // pixel-tile warp id
    const int prow = wp >> 1;
    const int pc   = (wp & 1) << 5;
    const int qr   = lane >> 2;
    const int gp   = lane & 3;
    const int start = wp * 9 + (wh << 2);   // stagger: SMSP-mates far apart mod 72

    const uint32_t abase = sb + (uint32_t)prow * PHI_R + (uint32_t)(pc + qr) * 32 + (uint32_t)gp * 8;
    const uint4* wq = ((const uint4*)g_Wfrag) + lane + (wh ? 64 : 0);  // nt base offset
    const uint2* offT = (const uint2*)(smem + OFF_TAB);

    float acc[2][2][4];
#pragma unroll
    for (int t = 0; t < 2; ++t)
#pragma unroll
        for (int n = 0; n < 2; ++n)
#pragma unroll
            for (int r = 0; r < 4; ++r) acc[t][n][r] = 0.f;

    // A double-buffer: iteration i lives in buffer (i & 1)
    uint32_t Ahb[2][8], Alb[2][8];
    {
        uint2 o0 = offT[start];
        lds_A(abase + o0.x, Ahb[0], Alb[0], 0);
        lds_A(abase + o0.y, Ahb[0], Alb[0], 2);
    }
    uint2 offn = offT[start + 1];

    // B ring: 4 chunks x 2 local nt in registers
    uint4 Bb[4][2];
#pragma unroll
    for (int j = 0; j < 4; ++j) {
        int kp = start + j; kp -= (kp >= 72) ? 72 : 0;
#pragma unroll
        for (int nl = 0; nl < 2; ++nl)
            Bb[j][nl] = wq[kp * 128 + nl * 32];
    }

#pragma unroll 4
    for (int i = 0; i < 72; ++i) {
        const int cur = i & 1;
        const int nxt = cur ^ 1;
        const int j   = i & 3;

        // A prefetch for iteration i+1 (wraps harmlessly at the end)
        lds_A(abase + offn.x, Ahb[nxt], Alb[nxt], 0);
        lds_A(abase + offn.y, Ahb[nxt], Alb[nxt], 2);
        offn = offT[start + i + 2];   // table has 144 entries; max index 140

        // 12 mma, pass-major (same-acc RAW distance 4)
#pragma unroll
        for (int t = 0; t < 2; ++t)
#pragma unroll
            for (int nl = 0; nl < 2; ++nl)
                mma16816(acc[t][nl], Ahb[cur] + t * 4, Bb[j][nl].x, Bb[j][nl].y);
#pragma unroll
        for (int t = 0; t < 2; ++t)
#pragma unroll
            for (int nl = 0; nl < 2; ++nl)
                mma16816(acc[t][nl], Alb[cur] + t * 4, Bb[j][nl].x, Bb[j][nl].y);
#pragma unroll
        for (int t = 0; t < 2; ++t)
#pragma unroll
            for (int nl = 0; nl < 2; ++nl)
                mma16816(acc[t][nl], Ahb[cur] + t * 4, Bb[j][nl].z, Bb[j][nl].w);

        // B prefetch for iteration i+4 (wrapped; always issued, slot j reuse)
        {
            int kp = start + i + 4;                 // <= 142
            kp -= (kp >= 72) ? 72 : 0;              // single subtract suffices
#pragma unroll
            for (int nl = 0; nl < 2; ++nl)
                Bb[j][nl] = wq[kp * 128 + nl * 32];
        }
    }

    // ---------------- Stage 4: per-o partial stats from registers ----------
    {
        float S[2][2], Q[2][2];
#pragma unroll
        for (int nl = 0; nl < 2; ++nl)
#pragma unroll
            for (int h = 0; h < 2; ++h) {
                float v0 = acc[0][nl][h],     v1 = acc[0][nl][h + 2];
                float v2 = acc[1][nl][h],     v3 = acc[1][nl][h + 2];
                S[nl][h] = (v0 + v1) + (v2 + v3);
                float q = __fmul_rn(v0, v0);
                q = fmaf(v1, v1, q); q = fmaf(v2, v2, q); q = fmaf(v3, v3, q);
                Q[nl][h] = q;
            }
#pragma unroll
        for (int off = 4; off <= 16; off <<= 1)
#pragma unroll
            for (int nl = 0; nl < 2; ++nl)
#pragma unroll
                for (int h = 0; h < 2; ++h) {
                    S[nl][h] += __shfl_xor_sync(0xFFFFFFFFu, S[nl][h], off);
                    Q[nl][h] += __shfl_xor_sync(0xFFFFFFFFu, Q[nl][h], off);
                }
        if (qr == 0) {
#pragma unroll
            for (int nl = 0; nl < 2; ++nl)
#pragma unroll
                for (int h = 0; h < 2; ++h) {
                    sred[w][nl][h][0][gp] = S[nl][h];
                    sred[w][nl][h][1][gp] = Q[nl][h];
                }
        }
        __syncthreads();
        if (tid < 32) {
            int o = tid;
            int nt = o >> 3, rem = o & 7, gpp = rem >> 1, h = rem & 1;
            int whalf = nt >> 1, ntl = nt & 1;
            float Ss = 0.f, Qq = 0.f;
#pragma unroll
            for (int ww = 0; ww < 8; ++ww) {
                Ss += sred[whalf * 8 + ww][ntl][h][0][gpp];
                Qq += sred[whalf * 8 + ww][ntl][h][1][gpp];
            }
            g_part[o * 128 + cta] = make_float2(Ss, Qq);
        }
    }

    grid_barrier(&g_bar1);

    // ---------------- Stage 5: BN params (deterministic) + apply + store ---
    if (tid < 256) {
        int o = tid >> 3, j = tid & 7;
        float Ss = 0.f, Qq = 0.f;
#pragma unroll
        for (int i = 0; i < 16; ++i) {
            float2 pq = g_part[o * 128 + j * 16 + i];
            Ss += pq.x; Qq += pq.y;
        }
#pragma unroll
        for (int off = 1; off <= 4; off <<= 1) {
            Ss += __shfl_xor_sync(0xFFFFFFFFu, Ss, off);
            Qq += __shfl_xor_sync(0xFFFFFFFFu, Qq, off);
        }
        if (j == 0) {
            float mean = Ss * (1.f / 32768.f);
            float var  = Qq * (1.f / 32768.f) - mean * mean;
            float sc = gamma[o] * rsqrtf(var + 1e-5f);
            bnp[o] = make_float2(sc, fmaf(-mean, sc, beta[o]));
        }
    }
    __syncthreads();

    {
        float* ob = out + ((size_t)b << 17) + (size_t)(r0 + prow) * 64;
#pragma unroll
        for (int t = 0; t < 2; ++t) {
            int col0 = pc + (t << 4) + qr;
#pragma unroll
            for (int nl = 0; nl < 2; ++nl) {
                int o0 = (wh * 2 + nl) * 8 + (gp << 1);
                float2 n0 = bnp[o0];
                float2 n1 = bnp[o0 + 1];
                float* p0 = ob + ((size_t)o0 << 12);
                p0[col0]            = fmaf(acc[t][nl][0], n0.x, n0.y);
                p0[4096 + col0]     = fmaf(acc[t][nl][1], n1.x, n1.y);
                p0[col0 + 8]        = fmaf(acc[t][nl][2], n0.x, n0.y);
                p0[4096 + col0 + 8] = fmaf(acc[t][nl][3], n1.x, n1.y);
            }
        }
    }
}

// ---------------------------------------------------------------------------
extern "C" void kernel_launch(void* const* d_in, const int* in_sizes, int n_in,
                              void* d_out, int out_size) {
    const float* x     = (const float*)d_in[0];
    const float* W     = (const float*)d_in[1];
    const float* gamma = (const float*)d_in[2];
    const float* beta  = (const float*)d_in[3];
    float* out = (float*)d_out;

    cudaFuncSetAttribute(kan_fused, cudaFuncAttributeMaxDynamicSharedMemorySize, SMEM_TOT);
    kan_fused<<<128, 512, SMEM_TOT>>>(x, W, gamma, beta, out);
}

// round 9
// speedup vs baseline: 1.3692x; 1.0567x over previous
#include <cuda_runtime.h>
#include <cuda_bf16.h>
#include <cstdint>

// Problem: B=8, C=16, H=W=64, O=32, K=3, S=1, P=1, G=8, D=144, Kdim=1152
// basis(v,g) = exp(-((v-grid_g)/h)^2) = ex2(-u^2), u = v*C1 + C2[g]
#define C1F 2.1019642153762872f

__device__ __constant__ float C2F[8] = {
     4.2039284307525744f,  3.0028060219661250f,  1.8016836131796750f,  0.6005612043932250f,
    -0.6005612043932250f, -1.8016836131796750f, -3.0028060219661250f, -4.2039284307525744f
};

// Device scratch (no allocation allowed)
__device__ __align__(16) unsigned char g_Wfrag[147456];   // bf16 hi/lo B fragments
__device__ __align__(16) float2 g_part[32 * 128];         // per-(o, cta) sum/sumsq
__device__ unsigned g_bar0 = 0, g_bar1 = 0;               // monotone barrier counters

// ---------------------------------------------------------------------------
// helpers
// ---------------------------------------------------------------------------
__device__ __forceinline__ float ex2f(float m) {
    float r; asm("ex2.approx.f32 %0, %1;" : "=f"(r) : "f"(m)); return r;
}
__device__ __forceinline__ uint32_t pack_hi(float b0, float b1) {
    uint32_t r, u0 = __float_as_uint(b0), u1 = __float_as_uint(b1);
    asm("prmt.b32 %0, %1, %2, 0x7632;" : "=r"(r) : "r"(u0), "r"(u1));
    return r;
}
__device__ __forceinline__ uint32_t pack_lo(float b0, float b1) {
    float l0 = b0 - __uint_as_float(__float_as_uint(b0) & 0xFFFF0000u);
    float l1 = b1 - __uint_as_float(__float_as_uint(b1) & 0xFFFF0000u);
    uint32_t r;
    asm("cvt.rn.bf16x2.f32 %0, %1, %2;" : "=r"(r) : "f"(l1), "f"(l0));
    return r;
}
__device__ __forceinline__ void mma16816(float* c, const uint32_t* a, uint32_t b0, uint32_t b1) {
    asm volatile(
        "mma.sync.aligned.m16n8k16.row.col.f32.bf16.bf16.f32 "
        "{%0,%1,%2,%3}, {%4,%5,%6,%7}, {%8,%9}, {%0,%1,%2,%3};"
        : "+f"(c[0]), "+f"(c[1]), "+f"(c[2]), "+f"(c[3])
        : "r"(a[0]), "r"(a[1]), "r"(a[2]), "r"(a[3]), "r"(b0), "r"(b1));
}
__device__ __forceinline__ uint32_t smem_u32(const void* p) {
    uint32_t a;
    asm("{ .reg .u64 t; cvta.to.shared.u64 t, %1; cvt.u32.u64 %0, t; }" : "=r"(a) : "l"(p));
    return a;
}
// Load Ah/Al for one d-value (4 pixel quads = 32 px) from Phi tile. half = 2*dl.
__device__ __forceinline__ void lds_A(uint32_t ta, uint32_t* Ah, uint32_t* Al, int half) {
    uint32_t h0, l0, h1, l1, h2, l2, h3, l3;
    asm("ld.shared.v2.b32 {%0,%1}, [%8];\n\t"
        "ld.shared.v2.b32 {%2,%3}, [%8+256];\n\t"
        "ld.shared.v2.b32 {%4,%5}, [%8+512];\n\t"
        "ld.shared.v2.b32 {%6,%7}, [%8+768];"
        : "=r"(h0), "=r"(l0), "=r"(h1), "=r"(l1),
          "=r"(h2), "=r"(l2), "=r"(h3), "=r"(l3)
        : "r"(ta));
    Ah[0 + half] = h0; Al[0 + half] = l0;   // q0 (t=0)
    Ah[1 + half] = h1; Al[1 + half] = l1;   // q1 (t=0)
    Ah[4 + half] = h2; Al[4 + half] = l2;   // q2 (t=1)
    Ah[5 + half] = h3; Al[5 + half] = l3;   // q3 (t=1)
}

// Grid barrier over exactly 128 co-resident CTAs. Monotone counter (graph-safe).
__device__ __forceinline__ void grid_barrier(unsigned* ctr) {
    __threadfence();
    __syncthreads();
    if (threadIdx.x == 0) {
        unsigned prev = atomicAdd(ctr, 1u);
        unsigned target = ((prev >> 7) + 1u) << 7;
        unsigned v;
        do {
            asm volatile("ld.acquire.gpu.global.u32 %0, [%1];" : "=r"(v) : "l"(ctr));
        } while ((int)(v - target) < 0);
    }
    __syncthreads();
}

// ---------------------------------------------------------------------------
// Single fused kernel. 128 CTAs x 512 thr (16 warps), 1 CTA/SM.
// k-SPLIT: warp (wp, wh) owns 32 pixels x ALL 32 outputs x 36 k-chunks
// (wh selects k-half). Halves A-LDS traffic vs o-split. Partial accumulators
// merged through (dead) Phi smem after the mainloop.
// ---------------------------------------------------------------------------
#define PHI_R 2112                      // 66 * 32 bytes
#define PHI_C 12672                     // 6 * PHI_R
#define OFF_TAB 202752                  // 16 * PHI_C
#define SMEM_TOT (202752 + 2304)        // + 2 x 72 uint4 schedule table

__global__ void __launch_bounds__(512, 1) kan_fused(
    const float* __restrict__ x, const float* __restrict__ W,
    const float* __restrict__ gamma, const float* __restrict__ beta,
    float* __restrict__ out)
{
    extern __shared__ char smem[];
    __shared__ float sred[8][4][2][2][4];   // [wp][nt][h][S/Q][gp]
    __shared__ float2 bnp[32];

    const uint32_t sb = smem_u32(smem);
    const int tid = threadIdx.x;
    const int cta = blockIdx.x;
    const int b   = cta >> 4;
    const int r0  = (cta & 15) << 2;

    // ---------------- Stage 1: Wsum slice (o fixed, 288 k-values) ----------
    {
        const int o  = cta >> 2;
        const int k0 = (cta & 3) * 288;
#pragma unroll 1
        for (int i = tid; i < 288; i += 512) {
            const int k = k0 + i;
            const float* p = W + (size_t)o * 165888 + k;
            float a0 = 0.f, a1 = 0.f, a2 = 0.f, a3 = 0.f;
#pragma unroll
            for (int d = 0; d < 144; d += 4) {
                a0 += p[(d + 0) * 1152];
                a1 += p[(d + 1) * 1152];
                a2 += p[(d + 2) * 1152];
                a3 += p[(d + 3) * 1152];
            }
            float s = (a0 + a1) + (a2 + a3);

            uint32_t sbits = __float_as_uint(s);
            unsigned short hib = (unsigned short)(sbits >> 16);
            float hif = __uint_as_float(sbits & 0xFFFF0000u);
            __nv_bfloat16 lo = __float2bfloat16(s - hif);

            int kc   = k >> 4;
            int kl   = k & 15;
            int slot = kl >> 1;
            int hi4  = slot >> 2;
            int s2   = slot & 3;
            int half = kl & 1;
            int base = kc * 2048 + o * 64 + s2 * 16;
            *(unsigned short*)(g_Wfrag + base + hi4 * 4 + half * 2)     = hib;
            *(unsigned short*)(g_Wfrag + base + 8 + hi4 * 4 + half * 2) = *(unsigned short*)&lo;
        }
    }

    // ---------------- Stage 2: Phi tile + schedule table --------------------
#pragma unroll 1
    for (int idx = tid; idx < 6336; idx += 512) {
        int c   = idx / 396;
        int rem = idx - c * 396;
        int r   = rem / 66;
        int col = rem - r * 66;
        int y  = r0 - 1 + r;
        int xx = col - 1;
        float v = 0.f;
        if ((unsigned)y < 64u && (unsigned)xx < 64u)
            v = x[(((b * 16 + c) << 6) + y) * 64 + xx];
        float bb[8];
#pragma unroll
        for (int g = 0; g < 8; ++g) {
            float u = fmaf(v, C1F, C2F[g]);
            bb[g] = ex2f(__fmul_rn(u, -u));
        }
        uint32_t hw[4], lw[4];
#pragma unroll
        for (int i = 0; i < 4; ++i) {
            hw[i] = pack_hi(bb[2 * i], bb[2 * i + 1]);
            lw[i] = pack_lo(bb[2 * i], bb[2 * i + 1]);
        }
        uint32_t a = sb + c * PHI_C + r * PHI_R + col * 32;
        asm volatile("st.shared.v4.b32 [%0], {%1,%2,%3,%4};"
                     :: "r"(a), "r"(hw[0]), "r"(lw[0]), "r"(hw[1]), "r"(lw[1]) : "memory");
        asm volatile("st.shared.v4.b32 [%0+16], {%1,%2,%3,%4};"
                     :: "r"(a), "r"(hw[2]), "r"(lw[2]), "r"(hw[3]), "r"(lw[3]) : "memory");
    }
    // schedule table: [wh][j], j in [0,72): chunk kc = wh*36 + (j mod 36)
    // entry = {phi offset d0, phi offset d1, kc*2048 (B byte off), 0}
    if (tid < 144) {
        int whh = (tid >= 72);
        int j   = tid - whh * 72;
        int jm  = j - (j >= 36 ? 36 : 0);
        int kc  = whh * 36 + jm;
        int d0 = 2 * kc, d1 = 2 * kc + 1;
        int c0 = d0 / 9, r90 = d0 - 9 * c0;
        int c1 = d1 / 9, r91 = d1 - 9 * c1;
        uint4 e;
        e.x = (uint32_t)(c0 * PHI_C + (r90 / 3) * PHI_R + (r90 % 3) * 32);
        e.y = (uint32_t)(c1 * PHI_C + (r91 / 3) * PHI_R + (r91 % 3) * 32);
        e.z = (uint32_t)(kc * 2048);
        e.w = 0u;
        ((uint4*)(smem + OFF_TAB))[tid] = e;
    }

    grid_barrier(&g_bar0);    // Wfrag globally ready; Phi + table smem ready

    // ---------------- Stage 3: mma mainloop (k-split, staggered) -----------
    const int lane = tid & 31;
    const int w    = tid >> 5;              // 0..15
    const int wh   = w >> 3;                // k-half
    const int wp   = w & 7;                 // pixel-tile warp id
    const int prow = wp >> 1;
    const int pc   = (wp & 1) << 5;
    const int qr   = lane >> 2;
    const int gp   = lane & 3;

    const uint32_t abase = sb + (uint32_t)prow * PHI_R + (uint32_t)(pc + qr) * 32 + (uint32_t)gp * 8;
    const unsigned char* wqB = g_Wfrag + lane * 16;
    const uint4* offT = (const uint4*)(smem + OFF_TAB) + wh * 72 + wp * 4;

    float acc[2][4][4];
#pragma unroll
    for (int t = 0; t < 2; ++t)
#pragma unroll
        for (int n = 0; n < 4; ++n)
#pragma unroll
            for (int r = 0; r < 4; ++r) acc[t][n][r] = 0.f;

    uint32_t Ah[8], Al[8];
    uint4 E1 = offT[0];
    uint4 E2 = offT[1];

    // B ring: 2 chunks x 4 nt
    uint4 Bb[2][4];
#pragma unroll
    for (int nl = 0; nl < 4; ++nl)
        Bb[0][nl] = *(const uint4*)(wqB + E1.z + nl * 512);
#pragma unroll
    for (int nl = 0; nl < 4; ++nl)
        Bb[1][nl] = *(const uint4*)(wqB + E2.z + nl * 512);

#pragma unroll 2
    for (int i = 0; i < 36; ++i) {
        const int cur = i & 1;

        // A for this chunk (single-buffer; staggered mates hide the LDS latency)
        lds_A(abase + E1.x, Ah, Al, 0);
        lds_A(abase + E1.y, Ah, Al, 2);
        uint4 E3 = offT[i + 2];   // table wrap-padded: max index wp*4+37 <= 65

        // 24 mma: HH, LH, HL passes (8 independent accs per pass)
#pragma unroll
        for (int t = 0; t < 2; ++t)
#pragma unroll
            for (int nl = 0; nl < 4; ++nl)
                mma16816(acc[t][nl], Ah + t * 4, Bb[cur][nl].x, Bb[cur][nl].y);
#pragma unroll
        for (int t = 0; t < 2; ++t)
#pragma unroll
            for (int nl = 0; nl < 4; ++nl)
                mma16816(acc[t][nl], Al + t * 4, Bb[cur][nl].x, Bb[cur][nl].y);
#pragma unroll
        for (int t = 0; t < 2; ++t)
#pragma unroll
            for (int nl = 0; nl < 4; ++nl)
                mma16816(acc[t][nl], Ah + t * 4, Bb[cur][nl].z, Bb[cur][nl].w);

        // B prefetch for chunk i+2 into the slot just consumed
#pragma unroll
        for (int nl = 0; nl < 4; ++nl)
            Bb[cur][nl] = *(const uint4*)(wqB + E3.z + nl * 512);

        E1 = E2; E2 = E3;
    }

    // ---------------- Merge k-halves through (dead) Phi smem ----------------
    __syncthreads();   // everyone past mainloop; Phi region reusable
    if (wh == 1) {
        // layout: [wp][rq (8)][lane][4 floats]  -> 32KB, conflict-free v4
        uint32_t mb = sb + (uint32_t)wp * 4096 + (uint32_t)lane * 16;
#pragma unroll
        for (int t = 0; t < 2; ++t)
#pragma unroll
            for (int nl = 0; nl < 4; ++nl) {
                uint32_t a = mb + (uint32_t)(t * 4 + nl) * 512;
                asm volatile("st.shared.v4.b32 [%0], {%1,%2,%3,%4};"
                             :: "r"(a),
                                "r"(__float_as_uint(acc[t][nl][0])),
                                "r"(__float_as_uint(acc[t][nl][1])),
                                "r"(__float_as_uint(acc[t][nl][2])),
                                "r"(__float_as_uint(acc[t][nl][3])) : "memory");
            }
    }
    __syncthreads();
    if (wh == 0) {
        uint32_t mb = sb + (uint32_t)wp * 4096 + (uint32_t)lane * 16;
#pragma unroll
        for (int t = 0; t < 2; ++t)
#pragma unroll
            for (int nl = 0; nl < 4; ++nl) {
                uint32_t a = mb + (uint32_t)(t * 4 + nl) * 512;
                float p0, p1, p2, p3;
                asm("ld.shared.v4.b32 {%0,%1,%2,%3}, [%4];"
                    : "=f"(p0), "=f"(p1), "=f"(p2), "=f"(p3) : "r"(a));
                acc[t][nl][0] += p0;
                acc[t][nl][1] += p1;
                acc[t][nl][2] += p2;
                acc[t][nl][3] += p3;
            }
    }

    // ---------------- Stage 4: per-o partial stats (wh==0 warps) -----------
    if (wh == 0) {
        float S[4][2], Q[4][2];
#pragma unroll
        for (int nl = 0; nl < 4; ++nl)
#pragma unroll
            for (int h = 0; h < 2; ++h) {
                float v0 = acc[0][nl][h],     v1 = acc[0][nl][h + 2];
                float v2 = acc[1][nl][h],     v3 = acc[1][nl][h + 2];
                S[nl][h] = (v0 + v1) + (v2 + v3);
                float q = __fmul_rn(v0, v0);
                q = fmaf(v1, v1, q); q = fmaf(v2, v2, q); q = fmaf(v3, v3, q);
                Q[nl][h] = q;
            }
#pragma unroll
        for (int off = 4; off <= 16; off <<= 1)
#pragma unroll
            for (int nl = 0; nl < 4; ++nl)
#pragma unroll
                for (int h = 0; h < 2; ++h) {
                    S[nl][h] += __shfl_xor_sync(0xFFFFFFFFu, S[nl][h], off);
                    Q[nl][h] += __shfl_xor_sync(0xFFFFFFFFu, Q[nl][h], off);
                }
        if (qr == 0) {
#pragma unroll
            for (int nl = 0; nl < 4; ++nl)
#pragma unroll
                for (int h = 0; h < 2; ++h) {
                    sred[wp][nl][h][0][gp] = S[nl][h];
                    sred[wp][nl][h][1][gp] = Q[nl][h];
                }
        }
    }
    __syncthreads();
    if (tid < 32) {
        int o = tid;
        int nt = o >> 3, rem = o & 7, gpp = rem >> 1, h = rem & 1;
        float Ss = 0.f, Qq = 0.f;
#pragma unroll
        for (int ww = 0; ww < 8; ++ww) {
            Ss += sred[ww][nt][h][0][gpp];
            Qq += sred[ww][nt][h][1][gpp];
        }
        g_part[o * 128 + cta] = make_float2(Ss, Qq);
    }

    grid_barrier(&g_bar1);

    // ---------------- Stage 5: BN params (deterministic) + apply + store ---
    if (tid < 256) {
        int o = tid >> 3, j = tid & 7;
        float Ss = 0.f, Qq = 0.f;
#pragma unroll
        for (int i = 0; i < 16; ++i) {
            float2 pq = g_part[o * 128 + j * 16 + i];
            Ss += pq.x; Qq += pq.y;
        }
#pragma unroll
        for (int off = 1; off <= 4; off <<= 1) {
            Ss += __shfl_xor_sync(0xFFFFFFFFu, Ss, off);
            Qq += __shfl_xor_sync(0xFFFFFFFFu, Qq, off);
        }
        if (j == 0) {
            float mean = Ss * (1.f / 32768.f);
            float var  = Qq * (1.f / 32768.f) - mean * mean;
            float sc = gamma[o] * rsqrtf(var + 1e-5f);
            bnp[o] = make_float2(sc, fmaf(-mean, sc, beta[o]));
        }
    }
    __syncthreads();

    if (wh == 0) {
        float* ob = out + ((size_t)b << 17) + (size_t)(r0 + prow) * 64;
#pragma unroll
        for (int t = 0; t < 2; ++t) {
            int col0 = pc + (t << 4) + qr;
#pragma unroll
            for (int nl = 0; nl < 4; ++nl) {
                int o0 = nl * 8 + (gp << 1);
                float2 n0 = bnp[o0];
                float2 n1 = bnp[o0 + 1];
                float* p0 = ob + ((size_t)o0 << 12);
                p0[col0]            = fmaf(acc[t][nl][0], n0.x, n0.y);
                p0[4096 + col0]     = fmaf(acc[t][nl][1], n1.x, n1.y);
                p0[col0 + 8]        = fmaf(acc[t][nl][2], n0.x, n0.y);
                p0[4096 + col0 + 8] = fmaf(acc[t][nl][3], n1.x, n1.y);
            }
        }
    }
}

// ---------------------------------------------------------------------------
extern "C" void kernel_launch(void* const* d_in, const int* in_sizes, int n_in,
                              void* d_out, int out_size) {
    const float* x     = (const float*)d_in[0];
    const float* W     = (const float*)d_in[1];
    const float* gamma = (const float*)d_in[2];
    const float* beta  = (const float*)d_in[3];
    float* out = (float*)d_out;

    cudaFuncSetAttribute(kan_fused, cudaFuncAttributeMaxDynamicSharedMemorySize, SMEM_TOT);
    kan_fused<<<128, 512, SMEM_TOT>>>(x, W, gamma, beta, out);
}

// round 10
// speedup vs baseline: 1.5303x; 1.1176x over previous
#include <cuda_runtime.h>
#include <cstdint>

// Problem: B=8, C=16, H=W=64, O=32, K=3, S=1, P=1, G=8, D=144, Kdim=1152
// basis(v,g) = exp(-((v-grid_g)/h)^2); 127*basis = exp2(-u^2 + log2(127)),
// u = v*C1 + C2[g]
#define C1F     2.1019642153762872f
#define LOG2127 6.988684686772166f

__device__ __constant__ float C2F[8] = {
     4.2039284307525744f,  3.0028060219661250f,  1.8016836131796750f,  0.6005612043932250f,
    -0.6005612043932250f, -1.8016836131796750f, -3.0028060219661250f, -4.2039284307525744f
};

// Device scratch (no allocation allowed)
__device__ __align__(16) unsigned char g_Wfrag8[73728];   // s8 2-digit B fragments
__device__ float g_pmax[128];                              // per-CTA partial max|Wsum|
__device__ __align__(16) float2 g_part[32 * 128];          // per-(o, cta) sum/sumsq
__device__ unsigned g_barA = 0, g_barB = 0, g_barC = 0;    // monotone barrier counters

// ---------------------------------------------------------------------------
// helpers
// ---------------------------------------------------------------------------
__device__ __forceinline__ float ex2f(float m) {
    float r; asm("ex2.approx.f32 %0, %1;" : "=f"(r) : "f"(m)); return r;
}
__device__ __forceinline__ uint32_t smem_u32(const void* p) {
    uint32_t a;
    asm("{ .reg .u64 t; cvta.to.shared.u64 t, %1; cvt.u32.u64 %0, t; }" : "=r"(a) : "l"(p));
    return a;
}
__device__ __forceinline__ void lds64(uint32_t a, uint32_t& h, uint32_t& l) {
    asm("ld.shared.v2.b32 {%0,%1}, [%2];" : "=r"(h), "=r"(l) : "r"(a));
}
__device__ __forceinline__ uint4 lds128(uint32_t a) {
    uint4 v;
    asm("ld.shared.v4.b32 {%0,%1,%2,%3}, [%4];"
        : "=r"(v.x), "=r"(v.y), "=r"(v.z), "=r"(v.w) : "r"(a));
    return v;
}
// s8 mma: D[16,8] s32 += A[16,32] s8 x B[32,8] s8
__device__ __forceinline__ void mmai(int* c, const uint32_t* a, uint32_t b0, uint32_t b1) {
    asm volatile(
        "mma.sync.aligned.m16n8k32.row.col.s32.s8.s8.s32 "
        "{%0,%1,%2,%3}, {%4,%5,%6,%7}, {%8,%9}, {%0,%1,%2,%3};"
        : "+r"(c[0]), "+r"(c[1]), "+r"(c[2]), "+r"(c[3])
        : "r"(a[0]), "r"(a[1]), "r"(a[2]), "r"(a[3]), "r"(b0), "r"(b1));
}

// Grid barrier over exactly 128 co-resident CTAs. Monotone counter (graph-safe).
__device__ __forceinline__ void grid_barrier(unsigned* ctr) {
    __threadfence();
    __syncthreads();
    if (threadIdx.x == 0) {
        unsigned prev = atomicAdd(ctr, 1u);
        unsigned target = ((prev >> 7) + 1u) << 7;
        unsigned v;
        do {
            asm volatile("ld.acquire.gpu.global.u32 %0, [%1];" : "=r"(v) : "l"(ctr));
        } while ((int)(v - target) < 0);
    }
    __syncthreads();
}

// ---------------------------------------------------------------------------
// Layout constants
// Phi int8: per x-element 16B = [h(g0-3) | l(g0-3) | h(g4-7) | l(g4-7)]
// ---------------------------------------------------------------------------
#define PHI_R8   1056                   // 66 cols * 16 B
#define PHI_C8   6336                   // 6 rows * PHI_R8
#define OFF_TAB8 101376                 // 16 ch * PHI_C8
#define SM_W     102528                 // OFF_TAB8 + 2*36*16
#define SMEM_TOT (102528 + 73728)       // + W fragment mirror = 176256 B

__global__ void __launch_bounds__(512, 1) kan_fused(
    const float* __restrict__ x, const float* __restrict__ W,
    const float* __restrict__ gamma, const float* __restrict__ beta,
    float* __restrict__ out)
{
    extern __shared__ char smem[];
    __shared__ float wmax[16];
    __shared__ float ssc[32];               // per-o scale m/127^2
    __shared__ float sred[8][4][2][2][4];   // [wp][nt][h][S/Q][gp]
    __shared__ float2 bnp[32];

    const uint32_t sb = smem_u32(smem);
    const int tid = threadIdx.x;
    const int cta = blockIdx.x;
    const int b   = cta >> 4;
    const int r0  = (cta & 15) << 2;

    // ---------------- Stage 1a: Wsum (o fixed, 288 k) + partial max --------
    float wsum_val = 0.f;
    {
        const int o  = cta >> 2;
        const int k0 = (cta & 3) * 288;
        float lm = 0.f;
        if (tid < 288) {
            const int k = k0 + tid;
            const float* p = W + (size_t)o * 165888 + k;
            float a0 = 0.f, a1 = 0.f, a2 = 0.f, a3 = 0.f;
#pragma unroll
            for (int d = 0; d < 144; d += 4) {
                a0 += p[(d + 0) * 1152];
                a1 += p[(d + 1) * 1152];
                a2 += p[(d + 2) * 1152];
                a3 += p[(d + 3) * 1152];
            }
            wsum_val = (a0 + a1) + (a2 + a3);
            lm = fabsf(wsum_val);
        }
#pragma unroll
        for (int off = 16; off; off >>= 1)
            lm = fmaxf(lm, __shfl_xor_sync(0xFFFFFFFFu, lm, off));
        if ((tid & 31) == 0) wmax[tid >> 5] = lm;
        __syncthreads();
        if (tid == 0) {
            float m = wmax[0];
#pragma unroll
            for (int i = 1; i < 16; ++i) m = fmaxf(m, wmax[i]);
            g_pmax[cta] = fmaxf(m, 1e-30f);
        }
    }

    // ---------------- Stage 2: Phi tile (int8 2-digit) + schedule table ----
#pragma unroll 1
    for (int idx = tid; idx < 6336; idx += 512) {
        int c   = idx / 396;
        int rem = idx - c * 396;
        int r   = rem / 66;
        int col = rem - r * 66;
        int y  = r0 - 1 + r;
        int xx = col - 1;
        float v = 0.f;
        if ((unsigned)y < 64u && (unsigned)xx < 64u)
            v = x[(((b * 16 + c) << 6) + y) * 64 + xx];
        uint32_t hw0 = 0, lw0 = 0, hw1 = 0, lw1 = 0;
#pragma unroll
        for (int g = 0; g < 8; ++g) {
            float u = fmaf(v, C1F, C2F[g]);
            float q = ex2f(fmaf(u, -u, LOG2127));      // 127 * basis, in [0,127]
            int ih = __float2int_rn(q);
            float hf = (float)ih;
            int il = __float2int_rn((q - hf) * 256.f);
            il = min(il, 127);
            int sh = (g & 3) << 3;
            if (g < 4) { hw0 |= (uint32_t)ih << sh; lw0 |= ((uint32_t)il & 0xFFu) << sh; }
            else       { hw1 |= (uint32_t)ih << sh; lw1 |= ((uint32_t)il & 0xFFu) << sh; }
        }
        uint32_t a = sb + c * PHI_C8 + r * PHI_R8 + col * 16;
        asm volatile("st.shared.v4.b32 [%0], {%1,%2,%3,%4};"
                     :: "r"(a), "r"(hw0), "r"(lw0), "r"(hw1), "r"(lw1) : "memory");
    }
    // schedule table: [wh][m in 0..36): chunk kc = wh*18 + (m mod 18)
    // entry = 4 words {off(d0), off(d2), off(d1), off(d3)}, d_i = 4kc+i
    if (tid < 72) {
        int whh = (tid >= 36);
        int m   = tid - whh * 36;
        int cj  = m - (m >= 18 ? 18 : 0);
        int kc  = whh * 18 + cj;
        uint32_t o4[4];
#pragma unroll
        for (int i = 0; i < 4; ++i) {
            int d = 4 * kc + i;
            int c = d / 9, r9 = d - 9 * c;
            o4[i] = (uint32_t)(c * PHI_C8 + (r9 / 3) * PHI_R8 + (r9 % 3) * 16);
        }
        uint32_t a = sb + OFF_TAB8 + tid * 16;
        asm volatile("st.shared.v4.b32 [%0], {%1,%2,%3,%4};"
                     :: "r"(a), "r"(o4[0]), "r"(o4[2]), "r"(o4[1]), "r"(o4[3]) : "memory");
    }

    grid_barrier(&g_barA);    // all g_pmax visible; Phi + table smem ready

    // ---------------- Stage 1b: quantize W -> global s8 fragments ----------
    if (tid < 288) {
        const int o  = cta >> 2;
        const int k  = (cta & 3) * 288 + tid;
        const float* pm = g_pmax + (cta & ~3);
        float m = fmaxf(fmaxf(pm[0], pm[1]), fmaxf(pm[2], pm[3]));
        float qf = wsum_val * (127.f / m);
        int ih = __float2int_rn(qf);
        float hf = (float)ih;
        int il = __float2int_rn((qf - hf) * 256.f);
        il = min(il, 127);
        int kc = k >> 5, kl = k & 31;
        int base = kc * 2048 + (o >> 3) * 512
                 + ((o & 7) * 4 + ((kl & 15) >> 2)) * 16
                 + ((kl >> 4) << 2) + (kl & 3);
        ((signed char*)g_Wfrag8)[base]     = (signed char)ih;
        ((signed char*)g_Wfrag8)[base + 8] = (signed char)il;
    }
    if (tid < 32) {
        const float* pm = g_pmax + tid * 4;
        float m = fmaxf(fmaxf(pm[0], pm[1]), fmaxf(pm[2], pm[3]));
        ssc[tid] = m * (1.f / 16129.f);       // m / 127^2
    }

    grid_barrier(&g_barB);    // W fragments globally complete

    // ---------------- Copy W fragments to smem ------------------------------
    {
        const uint4* src = (const uint4*)g_Wfrag8;
        uint4* dst = (uint4*)(smem + SM_W);
#pragma unroll
        for (int i = tid; i < 4608; i += 512) dst[i] = src[i];
    }
    __syncthreads();

    // ---------------- Stage 3: s8 mma mainloop (k-split, staggered) --------
    const int lane = tid & 31;
    const int w    = tid >> 5;
    const int wh   = w >> 3;                 // k-half
    const int wp   = w & 7;                  // pixel-tile warp id
    const int prow = wp >> 1;
    const int pc   = (wp & 1) << 5;
    const int qr   = lane >> 2;
    const int gp   = lane & 3;
    const int start = wp * 2 + wh;           // 0..15, SMSP-mates desynced

    const uint32_t abase = sb + (uint32_t)prow * PHI_R8
                         + (uint32_t)(pc + qr) * 16 + (uint32_t)(gp & 1) * 8;
    const uint32_t tb    = sb + OFF_TAB8 + (uint32_t)wh * 576
                         + (uint32_t)start * 16 + (uint32_t)(gp >> 1) * 8;
    const uint32_t swB   = sb + SM_W + (uint32_t)wh * 36864 + (uint32_t)lane * 16;

    int acch[2][4][4], accm[2][4][4];
#pragma unroll
    for (int t = 0; t < 2; ++t)
#pragma unroll
        for (int n = 0; n < 4; ++n)
#pragma unroll
            for (int r = 0; r < 4; ++r) { acch[t][n][r] = 0; accm[t][n][r] = 0; }

    uint32_t Eax, Eay;
    lds64(tb, Eax, Eay);
    int cjr = start;

#pragma unroll 3
    for (int j = 0; j < 18; ++j) {
        // ---- A fragments (h+l pairs), 8 x LDS.64 ----
        uint32_t Ah0[4], Al0[4], Ah1[4], Al1[4];
        {
            uint32_t aA = abase + Eax, aB = abase + Eay;
            lds64(aA,        Ah0[0], Al0[0]);
            lds64(aA + 128,  Ah0[1], Al0[1]);
            lds64(aB,        Ah0[2], Al0[2]);
            lds64(aB + 128,  Ah0[3], Al0[3]);
            lds64(aA + 256,  Ah1[0], Al1[0]);
            lds64(aA + 384,  Ah1[1], Al1[1]);
            lds64(aB + 256,  Ah1[2], Al1[2]);
            lds64(aB + 384,  Ah1[3], Al1[3]);
        }
        // ---- B fragments from smem, 4 x LDS.128 ----
        uint32_t bbase = swB + (uint32_t)cjr * 2048;
        uint4 Bb[4];
#pragma unroll
        for (int nl = 0; nl < 4; ++nl) Bb[nl] = lds128(bbase + nl * 512);

        // table prefetch for next iteration
        lds64(tb + (j + 1) * 16, Eax, Eay);

        // ---- 24 mma: HH -> acc_hi ; LH + HL -> acc_mid ----
#pragma unroll
        for (int nl = 0; nl < 4; ++nl) {
            mmai(acch[0][nl], Ah0, Bb[nl].x, Bb[nl].y);
            mmai(acch[1][nl], Ah1, Bb[nl].x, Bb[nl].y);
        }
#pragma unroll
        for (int nl = 0; nl < 4; ++nl) {
            mmai(accm[0][nl], Al0, Bb[nl].x, Bb[nl].y);
            mmai(accm[1][nl], Al1, Bb[nl].x, Bb[nl].y);
        }
#pragma unroll
        for (int nl = 0; nl < 4; ++nl) {
            mmai(accm[0][nl], Ah0, Bb[nl].z, Bb[nl].w);
            mmai(accm[1][nl], Ah1, Bb[nl].z, Bb[nl].w);
        }

        cjr = (cjr == 17) ? 0 : cjr + 1;
    }

    // ---------------- Merge k-halves exactly (int) through dead Phi smem ---
    __syncthreads();
    if (wh == 1) {
        uint32_t mb = sb + (uint32_t)wp * 8192 + (uint32_t)lane * 16;
#pragma unroll
        for (int t = 0; t < 2; ++t)
#pragma unroll
            for (int nl = 0; nl < 4; ++nl) {
                uint32_t a = mb + (uint32_t)(t * 4 + nl) * 512;
                asm volatile("st.shared.v4.b32 [%0], {%1,%2,%3,%4};"
                             :: "r"(a), "r"(acch[t][nl][0]), "r"(acch[t][nl][1]),
                                "r"(acch[t][nl][2]), "r"(acch[t][nl][3]) : "memory");
                asm volatile("st.shared.v4.b32 [%0], {%1,%2,%3,%4};"
                             :: "r"(a + 4096), "r"(accm[t][nl][0]), "r"(accm[t][nl][1]),
                                "r"(accm[t][nl][2]), "r"(accm[t][nl][3]) : "memory");
            }
    }
    __syncthreads();

    float cf[2][4][4];
    if (wh == 0) {
        uint32_t mb = sb + (uint32_t)wp * 8192 + (uint32_t)lane * 16;
#pragma unroll
        for (int t = 0; t < 2; ++t)
#pragma unroll
            for (int nl = 0; nl < 4; ++nl) {
                uint32_t a = mb + (uint32_t)(t * 4 + nl) * 512;
                int h0, h1, h2, h3, m0, m1, m2, m3;
                asm("ld.shared.v4.b32 {%0,%1,%2,%3}, [%4];"
                    : "=r"(h0), "=r"(h1), "=r"(h2), "=r"(h3) : "r"(a));
                asm("ld.shared.v4.b32 {%0,%1,%2,%3}, [%4];"
                    : "=r"(m0), "=r"(m1), "=r"(m2), "=r"(m3) : "r"(a + 4096));
                int H0 = acch[t][nl][0] + h0, M0 = accm[t][nl][0] + m0;
                int H1 = acch[t][nl][1] + h1, M1 = accm[t][nl][1] + m1;
                int H2 = acch[t][nl][2] + h2, M2 = accm[t][nl][2] + m2;
                int H3 = acch[t][nl][3] + h3, M3 = accm[t][nl][3] + m3;
                float s0 = ssc[nl * 8 + (gp << 1)];
                float s1 = ssc[nl * 8 + (gp << 1) + 1];
                const float i256 = 0.00390625f;
                cf[t][nl][0] = s0 * fmaf((float)M0, i256, (float)H0);
                cf[t][nl][1] = s1 * fmaf((float)M1, i256, (float)H1);
                cf[t][nl][2] = s0 * fmaf((float)M2, i256, (float)H2);
                cf[t][nl][3] = s1 * fmaf((float)M3, i256, (float)H3);
            }
    }

    // ---------------- Stage 4: per-o partial stats (wh==0 warps) -----------
    if (wh == 0) {
        float S[4][2], Q[4][2];
#pragma unroll
        for (int nl = 0; nl < 4; ++nl)
#pragma unroll
            for (int h = 0; h < 2; ++h) {
                float v0 = cf[0][nl][h],     v1 = cf[0][nl][h + 2];
                float v2 = cf[1][nl][h],     v3 = cf[1][nl][h + 2];
                S[nl][h] = (v0 + v1) + (v2 + v3);
                float q = __fmul_rn(v0, v0);
                q = fmaf(v1, v1, q); q = fmaf(v2, v2, q); q = fmaf(v3, v3, q);
                Q[nl][h] = q;
            }
#pragma unroll
        for (int off = 4; off <= 16; off <<= 1)
#pragma unroll
            for (int nl = 0; nl < 4; ++nl)
#pragma unroll
                for (int h = 0; h < 2; ++h) {
                    S[nl][h] += __shfl_xor_sync(0xFFFFFFFFu, S[nl][h], off);
                    Q[nl][h] += __shfl_xor_sync(0xFFFFFFFFu, Q[nl][h], off);
                }
        if (qr == 0) {
#pragma unroll
            for (int nl = 0; nl < 4; ++nl)
#pragma unroll
                for (int h = 0; h < 2; ++h) {
                    sred[wp][nl][h][0][gp] = S[nl][h];
                    sred[wp][nl][h][1][gp] = Q[nl][h];
                }
        }
    }
    __syncthreads();
    if (tid < 32) {
        int o = tid;
        int nt = o >> 3, rem = o & 7, gpp = rem >> 1, h = rem & 1;
        float Ss = 0.f, Qq = 0.f;
#pragma unroll
        for (int ww = 0; ww < 8; ++ww) {
            Ss += sred[ww][nt][h][0][gpp];
            Qq += sred[ww][nt][h][1][gpp];
        }
        g_part[o * 128 + cta] = make_float2(Ss, Qq);
    }

    grid_barrier(&g_barC);

    // ---------------- Stage 5: BN params (deterministic) + apply + store ---
    if (tid < 256) {
        int o = tid >> 3, jj = tid & 7;
        float Ss = 0.f, Qq = 0.f;
#pragma unroll
        for (int i = 0; i < 16; ++i) {
            float2 pq = g_part[o * 128 + jj * 16 + i];
            Ss += pq.x; Qq += pq.y;
        }
#pragma unroll
        for (int off = 1; off <= 4; off <<= 1) {
            Ss += __shfl_xor_sync(0xFFFFFFFFu, Ss, off);
            Qq += __shfl_xor_sync(0xFFFFFFFFu, Qq, off);
        }
        if (jj == 0) {
            float mean = Ss * (1.f / 32768.f);
            float var  = Qq * (1.f / 32768.f) - mean * mean;
            float sc = gamma[o] * rsqrtf(var + 1e-5f);
            bnp[o] = make_float2(sc, fmaf(-mean, sc, beta[o]));
        }
    }
    __syncthreads();

    if (wh == 0) {
        float* ob = out + ((size_t)b << 17) + (size_t)(r0 + prow) * 64;
#pragma unroll
        for (int t = 0; t < 2; ++t) {
            int col0 = pc + (t << 4) + qr;
#pragma unroll
            for (int nl = 0; nl < 4; ++nl) {
                int o0 = nl * 8 + (gp << 1);
                float2 n0 = bnp[o0];
                float2 n1 = bnp[o0 + 1];
                float* p0 = ob + ((size_t)o0 << 12);
                p0[col0]            = fmaf(cf[t][nl][0], n0.x, n0.y);
                p0[4096 + col0]     = fmaf(cf[t][nl][1], n1.x, n1.y);
                p0[col0 + 8]        = fmaf(cf[t][nl][2], n0.x, n0.y);
                p0[4096 + col0 + 8] = fmaf(cf[t][nl][3], n1.x, n1.y);
            }
        }
    }
}

// ---------------------------------------------------------------------------
extern "C" void kernel_launch(void* const* d_in, const int* in_sizes, int n_in,
                              void* d_out, int out_size) {
    const float* x     = (const float*)d_in[0];
    const float* W     = (const float*)d_in[1];
    const float* gamma = (const float*)d_in[2];
    const float* beta  = (const float*)d_in[3];
    float* out = (float*)d_out;

    cudaFuncSetAttribute(kan_fused, cudaFuncAttributeMaxDynamicSharedMemorySize, SMEM_TOT);
    kan_fused<<<128, 512, SMEM_TOT>>>(x, W, gamma, beta, out);
}